// round 3
// baseline (speedup 1.0000x reference)
#include <cuda_runtime.h>
#include <math.h>

// ---------------- static scratch (allocation-free rule) ----------------
__device__ float g_h   [2000*512];
__device__ float g_xA1 [4000*256];
__device__ float g_xB1 [4000*256];
__device__ float g_xA2 [4000*256];
__device__ float g_xB2 [4000*256];
__device__ float g_axu [4000*512];
__device__ float g_tc1 [4000*256];
__device__ float g_tc2 [4000*256];
__device__ float g_s0  [2u*2000*2000];
__device__ float g_T1  [2000*256];
__device__ float g_Ssym[256*256];
__device__ float g_wcat[256*512];
__device__ float g_bcat[512];
__device__ float g_cs  [2*4096];
__device__ float g_u   [2*2048];
__device__ float g_v   [2*2048];
__device__ float g_Rf  [2*2048];
__device__ float g_Cf  [2*2048];
__device__ float g_sq  [4*2048];
__device__ float g_gmax[2];
__device__ float g_part[5u*4000*256];   // split-K partials

// packed dual-fp32 FMA (Blackwell f32x2 pipe)
#define FMA2(d,a,b) asm("fma.rn.f32x2 %0, %1, %2, %0;" : "+l"(d) : "l"(a), "l"(b))

// ---------------- reductions ----------------
__device__ __forceinline__ float warpReduceSum(float v){
#pragma unroll
    for (int o=16;o;o>>=1) v += __shfl_xor_sync(0xffffffffu, v, o);
    return v;
}
__device__ __forceinline__ float warpReduceMax(float v){
#pragma unroll
    for (int o=16;o;o>>=1) v = fmaxf(v, __shfl_xor_sync(0xffffffffu, v, o));
    return v;
}
__device__ __forceinline__ float blockReduceSum256(float v){
    __shared__ float sm[8];
    float w = warpReduceSum(v);
    int wi = threadIdx.x>>5, ln = threadIdx.x&31;
    if (ln==0) sm[wi] = w;
    __syncthreads();
    if (wi==0){ float t = (ln<8)?sm[ln]:0.f; t = warpReduceSum(t); if (ln==0) sm[0]=t; }
    __syncthreads();
    float r = sm[0];
    __syncthreads();
    return r;
}
__device__ __forceinline__ float blockReduceMax256(float v){
    __shared__ float sm[8];
    float w = warpReduceMax(v);
    int wi = threadIdx.x>>5, ln = threadIdx.x&31;
    if (ln==0) sm[wi] = w;
    __syncthreads();
    if (wi==0){ float t = (ln<8)?sm[ln]:-1e30f; t = warpReduceMax(t); if (ln==0) sm[0]=t; }
    __syncthreads();
    float r = sm[0];
    __syncthreads();
    return r;
}

// ---------------- generic fp32 GEMM, FFMA2 core, reg-staged pipeline ----------
// split-K over gridDim.z (raw partials at C + z*pstride), else fused epilogue:
// C = act( A @ (kscale.*B) + bias + addend (+C if accum) ) .* mscale
// act: 0 none, 1 relu, 2 sigmoid, 3 dist.
#define BM 128
#define BN 64
#define BK 16

template<bool TA, bool TB>
__global__ __launch_bounds__(256,2) void gemm_k(
    int M, int N, int K, int chunk, size_t pstride,
    const float* __restrict__ A, int lda,
    const float* __restrict__ B, int ldb,
    float* __restrict__ C, int ldc,
    const float* __restrict__ bias,
    const float* __restrict__ kscale,
    const float* __restrict__ mscale,
    const float* __restrict__ addend, int ldadd,
    int act, int accum,
    const float* __restrict__ xsq, const float* __restrict__ ysq,
    float* __restrict__ gmax)
{
    __shared__ float As[BK][BM+4];      // [k][m]
    __shared__ float Bs[BK][2*BN+8];    // [k][2n] duplicated pairs {b,b}
    int tid = threadIdx.x;
    int m0 = blockIdx.y * BM;
    int n0 = blockIdx.x * BN;
    int tx = tid & 15, ty = tid >> 4;
    int ml = ty*8, nl = tx*4;

    int kbeg = blockIdx.z * chunk;
    int kend = kbeg + chunk; if (kend > K) kend = K;

    const float4 zero4 = make_float4(0.f,0.f,0.f,0.f);
    float4 rA0, rA1, rB;

    auto loadA = [&](int k0){
        if (!TA){
            int row0 = tid >> 2,        kc0 = (tid & 3) << 2;
            int row1 = (256+tid) >> 2,  kc1 = kc0;
            rA0 = (m0+row0 < M) ? *(const float4*)(A + (size_t)(m0+row0)*lda + k0 + kc0) : zero4;
            rA1 = (m0+row1 < M) ? *(const float4*)(A + (size_t)(m0+row1)*lda + k0 + kc1) : zero4;
        } else {
            int kk0 = tid >> 5,       mc0 = (tid & 31) << 2;
            int kk1 = (256+tid) >> 5, mc1 = mc0;
            rA0 = (m0+mc0 < M) ? *(const float4*)(A + (size_t)(k0+kk0)*lda + m0 + mc0) : zero4;
            rA1 = (m0+mc1 < M) ? *(const float4*)(A + (size_t)(k0+kk1)*lda + m0 + mc1) : zero4;
        }
    };
    auto storeA = [&](){
        if (!TA){
            int row0 = tid >> 2, kc = (tid & 3) << 2;
            int row1 = (256+tid) >> 2;
            As[kc+0][row0]=rA0.x; As[kc+1][row0]=rA0.y; As[kc+2][row0]=rA0.z; As[kc+3][row0]=rA0.w;
            As[kc+0][row1]=rA1.x; As[kc+1][row1]=rA1.y; As[kc+2][row1]=rA1.z; As[kc+3][row1]=rA1.w;
        } else {
            int kk0 = tid >> 5, mc = (tid & 31) << 2;
            int kk1 = (256+tid) >> 5;
            *(float4*)(&As[kk0][mc]) = rA0;
            *(float4*)(&As[kk1][mc]) = rA1;
        }
    };
    auto loadB = [&](int k0){
        if (!TB){
            int kk = tid >> 4, nc = (tid & 15) << 2;
            rB = (n0+nc < N) ? *(const float4*)(B + (size_t)(k0+kk)*ldb + n0 + nc) : zero4;
            if (kscale){ float s = kscale[k0+kk]; rB.x*=s; rB.y*=s; rB.z*=s; rB.w*=s; }
        } else {
            int nr = tid >> 2, kc = (tid & 3) << 2;
            rB = (n0+nr < N) ? *(const float4*)(B + (size_t)(n0+nr)*ldb + k0 + kc) : zero4;
            if (kscale){
                rB.x *= kscale[k0+kc+0]; rB.y *= kscale[k0+kc+1];
                rB.z *= kscale[k0+kc+2]; rB.w *= kscale[k0+kc+3];
            }
        }
    };
    auto storeB = [&](){
        if (!TB){
            int kk = tid >> 4, nc = (tid & 15) << 2;
            float4 d0 = make_float4(rB.x,rB.x,rB.y,rB.y);
            float4 d1 = make_float4(rB.z,rB.z,rB.w,rB.w);
            *(float4*)(&Bs[kk][2*nc])   = d0;
            *(float4*)(&Bs[kk][2*nc+4]) = d1;
        } else {
            int nr = tid >> 2, kc = (tid & 3) << 2;
            Bs[kc+0][2*nr]=rB.x; Bs[kc+0][2*nr+1]=rB.x;
            Bs[kc+1][2*nr]=rB.y; Bs[kc+1][2*nr+1]=rB.y;
            Bs[kc+2][2*nr]=rB.z; Bs[kc+2][2*nr+1]=rB.z;
            Bs[kc+3][2*nr]=rB.w; Bs[kc+3][2*nr+1]=rB.w;
        }
    };

    unsigned long long acc2[4][4];
#pragma unroll
    for (int i=0;i<4;++i)
#pragma unroll
        for (int j=0;j<4;++j) acc2[i][j] = 0ull;

    // prologue
    loadA(kbeg); loadB(kbeg);
    storeA(); storeB();
    __syncthreads();

    for (int k0 = kbeg; k0 < kend; k0 += BK){
        bool next = (k0 + BK) < kend;
        if (next){ loadA(k0+BK); loadB(k0+BK); }
#pragma unroll
        for (int kk=0; kk<BK; ++kk){
            ulonglong2 a01 = *(const ulonglong2*)(&As[kk][ml]);      // {a0,a1},{a2,a3}
            ulonglong2 a23 = *(const ulonglong2*)(&As[kk][ml+4]);    // {a4,a5},{a6,a7}
            ulonglong2 b01 = *(const ulonglong2*)(&Bs[kk][2*nl]);    // {b0,b0},{b1,b1}
            ulonglong2 b23 = *(const ulonglong2*)(&Bs[kk][2*nl+4]);  // {b2,b2},{b3,b3}
            unsigned long long av[4] = {a01.x, a01.y, a23.x, a23.y};
            unsigned long long bv[4] = {b01.x, b01.y, b23.x, b23.y};
#pragma unroll
            for (int ip=0; ip<4; ++ip)
#pragma unroll
                for (int j=0; j<4; ++j) FMA2(acc2[ip][j], av[ip], bv[j]);
        }
        if (next){
            __syncthreads();
            storeA(); storeB();
            __syncthreads();
        }
    }

    // unpack: acc2[ip][j] = rows(2ip, 2ip+1), col j
    float accf[8][4];
#pragma unroll
    for (int ip=0; ip<4; ++ip)
#pragma unroll
        for (int j=0; j<4; ++j){
            unsigned long long vv = acc2[ip][j];
            accf[2*ip+0][j] = __uint_as_float((unsigned)(vv & 0xffffffffu));
            accf[2*ip+1][j] = __uint_as_float((unsigned)(vv >> 32));
        }

    if (gridDim.z > 1){
        float* Cp = C + (size_t)blockIdx.z * pstride;
#pragma unroll
        for (int i=0;i<8;++i){
            int gm = m0 + ml + i;
            if (gm < M){
#pragma unroll
                for (int j=0;j<4;++j){
                    int gn = n0 + nl + j;
                    if (gn < N) Cp[(size_t)gm*ldc + gn] = accf[i][j];
                }
            }
        }
        return;
    }

    float dmax = 0.f;
#pragma unroll
    for (int i=0;i<8;++i){
        int gm = m0 + ml + i;
        if (gm < M){
#pragma unroll
            for (int j=0;j<4;++j){
                int gn = n0 + nl + j;
                if (gn < N){
                    float v = accf[i][j];
                    size_t cidx = (size_t)gm*ldc + gn;
                    if (accum)  v += C[cidx];
                    if (addend) v += addend[(size_t)gm*ldadd + gn];
                    if (bias)   v += bias[gn];
                    if (act==1)      v = fmaxf(v, 0.f);
                    else if (act==2) v = 1.f/(1.f+expf(-v));
                    else if (act==3){
                        v = sqrtf(fmaxf(xsq[gm]+ysq[gn]-2.f*v, 0.f));
                        dmax = fmaxf(dmax, v);
                    }
                    if (mscale) v *= mscale[gm];
                    C[cidx] = v;
                }
            }
        }
    }
    if (act==3){
        __shared__ float red[256];
        red[tid] = dmax; __syncthreads();
        for (int s=128;s;s>>=1){ if (tid<s) red[tid]=fmaxf(red[tid],red[tid+s]); __syncthreads(); }
        if (tid==0) atomicMax((int*)gmax, __float_as_int(red[0]));
    }
}

// ---------------- split-K reducer ----------------
__global__ void reduce_k(const float* __restrict__ part, size_t pstride, int SK,
                         const float* __restrict__ addend, int ldadd,
                         const float* __restrict__ bias,
                         const float* __restrict__ rowscale,
                         float* __restrict__ out,
                         float* __restrict__ sqout, int mode)
{
    int row = blockIdx.x, t = threadIdx.x;
    float v = 0.f;
    for (int z=0; z<SK; ++z) v += part[(size_t)z*pstride + (size_t)row*256 + t];
    if (addend) v += addend[(size_t)row*ldadd + t];
    if (bias)   v += bias[t];
    if (mode==1){
        float s = blockReduceSum256(v*v);
        v /= fmaxf(sqrtf(s), 1e-12f);
        if (sqout && t==0) sqout[row] = 1.f;
    } else if (mode==2){
        v = 1.f/(1.f+expf(-v));
        float s = blockReduceSum256(v*v);
        if (sqout && t==0) sqout[row] = s;
    }
    if (rowscale) v *= rowscale[row];
    out[(size_t)row*256 + t] = v;
}

// ---------------- elementwise / misc kernels ----------------
__global__ void zero_k(float* p, int n){
    int i = blockIdx.x*blockDim.x + threadIdx.x;
    if (i < n) p[i] = 0.f;
}
__global__ void recip_clamp_k(float* p, int n){
    int i = blockIdx.x*blockDim.x + threadIdx.x;
    if (i < n) p[i] = 1.f / fmaxf(p[i], 1e-12f);
}
__global__ void simfin_k(float* __restrict__ p, const float* __restrict__ gmax, int n){
    int i = blockIdx.x*blockDim.x + threadIdx.x;
    if (i < n){
        float inv = 1.f / gmax[0];
        p[i] = 1.f - p[i]*inv;
    }
}
__global__ void colabs_k(const float* __restrict__ A, float* __restrict__ acc){
    int j  = blockIdx.x*256 + threadIdx.x;
    int r0 = blockIdx.y*125;
    if (j >= 4000) return;
    float s = 0.f;
    for (int i=0;i<125;++i) s += fabsf(A[(size_t)(r0+i)*4000 + j]);
    atomicAdd(&acc[j], s);
}
__global__ void ssym_k(const float* __restrict__ A, float* __restrict__ S){
    int i = blockIdx.x, j = threadIdx.x;
    S[i*256+j] = 0.5f*(A[i*256+j] + A[j*256+i]);
}
__global__ void pack_k(const float* __restrict__ wa, const float* __restrict__ wu,
                       const float* __restrict__ ba, const float* __restrict__ bu,
                       float* __restrict__ wcat, float* __restrict__ bcat){
    int r = blockIdx.x, n = threadIdx.x;
    wcat[r*512 + n] = (n < 256) ? wa[r*256 + n] : wu[r*256 + (n-256)];
    if (r == 0) bcat[n] = (n < 256) ? ba[n] : bu[n-256];
}
__global__ void softmax_k(float* __restrict__ s0base){
    int z = blockIdx.y, row = blockIdx.x, tid = threadIdx.x;
    float* p = s0base + (size_t)z*4000000 + (size_t)row*2000;
    float a[8]; float mx = -1e30f;
#pragma unroll
    for (int i=0;i<8;++i){
        int c = tid + i*256;
        if (c < 2000){ a[i] = 200.f*p[c]; mx = fmaxf(mx, a[i]); }
        else a[i] = -1e30f;
    }
    float rowmax = blockReduceMax256(mx);
    float Mx = fmaxf(rowmax, 0.f);
    float lsum = 0.f;
#pragma unroll
    for (int i=0;i<8;++i){
        int c = tid + i*256;
        if (c < 2000){ a[i] = expf(a[i]-Mx); lsum += a[i]; }
    }
    float tot = blockReduceSum256(lsum) + 2000.f*expf(-Mx);
    float inv = 1.f/tot;
#pragma unroll
    for (int i=0;i<8;++i){
        int c = tid + i*256;
        if (c < 2000) p[c] = a[i]*inv + 1e-4f;
    }
}
__global__ void sink_col_k(const float* __restrict__ s0base, const float* __restrict__ vraw,
                           float* __restrict__ uraw, int first){
    int z = blockIdx.z;
    const float* s0 = s0base + (size_t)z*4000000;
    __shared__ float Rs[125];
    int r0 = blockIdx.y*125;
    if (threadIdx.x < 125)
        Rs[threadIdx.x] = first ? 1.f : 1.f/vraw[z*2048 + r0 + threadIdx.x];
    __syncthreads();
    int j = blockIdx.x*256 + threadIdx.x;
    if (j < 2000){
        float s = 0.f;
        for (int i=0;i<125;++i) s += s0[(size_t)(r0+i)*2000 + j]*Rs[i];
        atomicAdd(&uraw[z*2048 + j], s);
    }
}
__global__ void sink_row_k(const float* __restrict__ s0base, const float* __restrict__ uraw,
                           float* __restrict__ vraw){
    int z = blockIdx.y;
    const float* s0 = s0base + (size_t)z*4000000;
    __shared__ float Cs[2000];
    for (int i=threadIdx.x; i<2000; i+=256) Cs[i] = 1.f/uraw[z*2048 + i];
    __syncthreads();
    int w = threadIdx.x>>5, lane = threadIdx.x&31;
    int row = blockIdx.x*8 + w;
    const float* pr = s0 + (size_t)row*2000;
    float s = 0.f;
    for (int j=lane; j<2000; j+=32) s += pr[j]*Cs[j];
#pragma unroll
    for (int o=16;o;o>>=1) s += __shfl_down_sync(0xffffffffu, s, o);
    if (lane==0) vraw[z*2048 + row] = s;
}
__global__ void scales_k(const float* __restrict__ uraw, const float* __restrict__ vraw,
                         float* __restrict__ Cf, float* __restrict__ Rf){
    int z = blockIdx.y;
    int i = blockIdx.x*256 + threadIdx.x;
    if (i < 2000){
        Cf[z*2048+i] = 1.f/uraw[z*2048+i];
        Rf[z*2048+i] = 1.f/vraw[z*2048+i];
    }
}
__global__ void write_s_k(float* __restrict__ out, const float* __restrict__ s0base,
                          const float* __restrict__ Rf, const float* __restrict__ Cf){
    int row = blockIdx.y;
    int col = blockIdx.x*256 + threadIdx.x;
    if (col >= 4000) return;
    float v = 0.f;
    if (row < 2000 && col < 2000)
        v = s0base[(size_t)row*2000 + col] * Rf[row] * Cf[col];
    else if (row >= 2000 && col >= 2000)
        v = s0base[4000000 + (size_t)(row-2000)*2000 + (col-2000)]
            * Rf[2048 + row-2000] * Cf[2048 + col-2000];
    out[(size_t)row*4000 + col] = v;
}

// ---------------- host-side GEMM dispatch ----------------
static void run_gemm(int ta, int tb, int M, int N, int K,
                     const float* A, int lda, const float* B, int ldb,
                     float* C, int ldc,
                     const float* bias, const float* ks, const float* ms,
                     const float* add, int ldadd, int act, int accum,
                     const float* xsq, const float* ysq, float* gmax)
{
    dim3 grid((N+BN-1)/BN, (M+BM-1)/BM, 1);
    if (!ta && !tb)      gemm_k<false,false><<<grid,256>>>(M,N,K,K,0,A,lda,B,ldb,C,ldc,bias,ks,ms,add,ldadd,act,accum,xsq,ysq,gmax);
    else if (!ta && tb)  gemm_k<false,true ><<<grid,256>>>(M,N,K,K,0,A,lda,B,ldb,C,ldc,bias,ks,ms,add,ldadd,act,accum,xsq,ysq,gmax);
    else                 gemm_k<true ,false><<<grid,256>>>(M,N,K,K,0,A,lda,B,ldb,C,ldc,bias,ks,ms,add,ldadd,act,accum,xsq,ysq,gmax);
}
static void run_gemm_split(int ta, int M, int N, int K,
                           const float* A, int lda, const float* B, int ldb,
                           float* part, const float* ks, int SK, int chunk)
{
    dim3 grid((N+BN-1)/BN, (M+BM-1)/BM, SK);
    size_t ps = (size_t)M*N;
    if (!ta) gemm_k<false,false><<<grid,256>>>(M,N,K,chunk,ps,A,lda,B,ldb,part,N,0,ks,0,0,0,0,0,0,0,0);
    else     gemm_k<true ,false><<<grid,256>>>(M,N,K,chunk,ps,A,lda,B,ldb,part,N,0,ks,0,0,0,0,0,0,0,0);
}

extern "C" void kernel_launch(void* const* d_in, const int* in_sizes, int n_in,
                              void* d_out, int out_size)
{
    (void)in_sizes; (void)n_in; (void)out_size;
    const float* emb1      = (const float*)d_in[0];
    const float* emb2      = (const float*)d_in[1];
    const float* edge1     = (const float*)d_in[2];
    const float* edge2     = (const float*)d_in[3];
    const float* Asrc      = (const float*)d_in[4];
    const float* Atgt      = (const float*)d_in[5];
    const float* fc1n_w    = (const float*)d_in[6];
    const float* fc1n_b    = (const float*)d_in[7];
    const float* fc2n_w    = (const float*)d_in[8];
    const float* fc2n_b    = (const float*)d_in[9];
    const float* fc1e_w    = (const float*)d_in[10];
    const float* fc1e_b    = (const float*)d_in[11];
    const float* fc2e_w    = (const float*)d_in[12];
    const float* fc2e_b    = (const float*)d_in[13];
    const float* gnn_a_w   = (const float*)d_in[14];
    const float* gnn_a_b   = (const float*)d_in[15];
    const float* gnn_u_w   = (const float*)d_in[16];
    const float* gnn_u_b   = (const float*)d_in[17];
    const float* aff_A     = (const float*)d_in[18];
    const float* cg_w      = (const float*)d_in[19];
    const float* cg_b      = (const float*)d_in[20];

    float* out_s  = (float*)d_out;
    float* out_kp = out_s + 16000000;
    float* out_ke = out_s + 20000000;

    float *h,*xA1,*xB1,*xA2,*xB2,*axu,*tc1,*tc2,*s0,*T1,*Ssym,*wcat,*bcat;
    float *cs,*u,*v,*Rf,*Cf,*sq,*gmax,*part;
    cudaGetSymbolAddress((void**)&h,    g_h);
    cudaGetSymbolAddress((void**)&xA1,  g_xA1);
    cudaGetSymbolAddress((void**)&xB1,  g_xB1);
    cudaGetSymbolAddress((void**)&xA2,  g_xA2);
    cudaGetSymbolAddress((void**)&xB2,  g_xB2);
    cudaGetSymbolAddress((void**)&axu,  g_axu);
    cudaGetSymbolAddress((void**)&tc1,  g_tc1);
    cudaGetSymbolAddress((void**)&tc2,  g_tc2);
    cudaGetSymbolAddress((void**)&s0,   g_s0);
    cudaGetSymbolAddress((void**)&T1,   g_T1);
    cudaGetSymbolAddress((void**)&Ssym, g_Ssym);
    cudaGetSymbolAddress((void**)&wcat, g_wcat);
    cudaGetSymbolAddress((void**)&bcat, g_bcat);
    cudaGetSymbolAddress((void**)&cs,   g_cs);
    cudaGetSymbolAddress((void**)&u,    g_u);
    cudaGetSymbolAddress((void**)&v,    g_v);
    cudaGetSymbolAddress((void**)&Rf,   g_Rf);
    cudaGetSymbolAddress((void**)&Cf,   g_Cf);
    cudaGetSymbolAddress((void**)&sq,   g_sq);
    cudaGetSymbolAddress((void**)&gmax, g_gmax);
    cudaGetSymbolAddress((void**)&part, g_part);

    const float* Aidx[2] = {Asrc, Atgt};
    float* cur[2] = {xA1, xA2};
    float* alt[2] = {xB1, xB2};

    // ---------- Stage A: node/edge embedding MLPs ----------
    run_gemm(0,0, 2000,512,128, emb1,128, fc1n_w,512, h,512, fc1n_b,0,0,0,0,1,0,0,0,0);
    run_gemm_split(0, 2000,256,512, h,512, fc2n_w,256, part, 0, 4, 128);
    reduce_k<<<2000,256>>>(part, 2000*256, 4, 0,0, fc2n_b, 0, cur[0], sq+0, 1);
    run_gemm(0,0, 2000,512,128, emb2,128, fc1n_w,512, h,512, fc1n_b,0,0,0,0,1,0,0,0,0);
    run_gemm_split(0, 2000,256,512, h,512, fc2n_w,256, part, 0, 4, 128);
    reduce_k<<<2000,256>>>(part, 2000*256, 4, 0,0, fc2n_b, 0, cur[1], sq+2048, 1);
    run_gemm(0,0, 2000,512,128, edge1,128, fc1e_w,512, h,512, fc1e_b,0,0,0,0,1,0,0,0,0);
    run_gemm_split(0, 2000,256,512, h,512, fc2e_w,256, part, 0, 4, 128);
    reduce_k<<<2000,256>>>(part, 2000*256, 4, 0,0, fc2e_b, 0, cur[0]+2000*256, sq+4096, 2);
    run_gemm(0,0, 2000,512,128, edge2,128, fc1e_w,512, h,512, fc1e_b,0,0,0,0,1,0,0,0,0);
    run_gemm_split(0, 2000,256,512, h,512, fc2e_w,256, part, 0, 4, 128);
    reduce_k<<<2000,256>>>(part, 2000*256, 4, 0,0, fc2e_b, 0, cur[1]+2000*256, sq+6144, 2);

    // ---------- Kp / Ke pairwise similarity ----------
    zero_k<<<1,32>>>(gmax, 2);
    run_gemm(0,1, 2000,2000,256, cur[0],256, cur[1],256, out_kp,2000,
             0,0,0,0,0, 3,0, sq+0,   sq+2048, gmax+0);
    run_gemm(0,1, 2000,2000,256, cur[0]+2000*256,256, cur[1]+2000*256,256, out_ke,2000,
             0,0,0,0,0, 3,0, sq+4096, sq+6144, gmax+1);
    simfin_k<<<(4000000+255)/256,256>>>(out_kp, gmax+0, 4000000);
    simfin_k<<<(4000000+255)/256,256>>>(out_ke, gmax+1, 4000000);

    // ---------- A column L1 sums -> reciprocal scales ----------
    zero_k<<<(8192+255)/256,256>>>(cs, 8192);
    colabs_k<<<dim3(16,32),256>>>(Asrc, cs);
    colabs_k<<<dim3(16,32),256>>>(Atgt, cs+4096);
    recip_clamp_k<<<(8192+255)/256,256>>>(cs, 8192);

    // ---------- GNN layers ----------
    for (int i=0; i<3; ++i){
        pack_k<<<256,512>>>(gnn_a_w + (size_t)i*65536, gnn_u_w + (size_t)i*65536,
                            gnn_a_b + (size_t)i*256,   gnn_u_b + (size_t)i*256,
                            wcat, bcat);

        for (int g=0; g<2; ++g){
            run_gemm(0,0, 4000,512,256, cur[g],256, wcat,512, axu,512, bcat,0,0,0,0,1,0,0,0,0);
            run_gemm_split(0, 4000,256,4000, Aidx[g],4000, axu,512, part, cs+g*4096, 5, 800);
            reduce_k<<<4000,256>>>(part, 4000*256, 5, axu+256,512, 0, 0, alt[g], 0, 1);
            float* t_ = cur[g]; cur[g] = alt[g]; alt[g] = t_;
        }

        if (i >= 1){
            ssym_k<<<256,256>>>(aff_A + (size_t)i*65536, Ssym);
            for (int z=0; z<2; ++z){
                size_t off = (size_t)z*2000*256;
                run_gemm_split(0, 2000,256,256, cur[0]+off,256, Ssym,256, part, 0, 2, 128);
                reduce_k<<<2000,256>>>(part, 2000*256, 2, 0,0, 0, 0, T1, 0, 0);
                run_gemm(0,1, 2000,2000,256, T1,256, cur[1]+off,256, s0 + (size_t)z*4000000,2000,
                         0,0,0,0,0,0,0,0,0,0);
            }
            softmax_k<<<dim3(2000,2),256>>>(s0);
            for (int t=0; t<10; ++t){
                if ((t & 1) == 0){
                    zero_k<<<(4096+255)/256,256>>>(u, 4096);
                    sink_col_k<<<dim3(8,16,2),256>>>(s0, v, u, (t==0)?1:0);
                } else {
                    sink_row_k<<<dim3(250,2),256>>>(s0, u, v);
                }
            }
            scales_k<<<dim3(8,2),256>>>(u, v, Cf, Rf);

            if (i == 1){
                for (int z=0; z<2; ++z){
                    size_t off = (size_t)z*2000*256;
                    run_gemm_split(0, 2000,256,2000, s0+(size_t)z*4000000,2000, cur[1]+off,256,
                                   part, Cf+z*2048, 5, 400);
                    reduce_k<<<2000,256>>>(part, 2000*256, 5, 0,0, 0, Rf+z*2048, tc1+off, 0, 0);
                    run_gemm_split(1, 2000,256,2000, s0+(size_t)z*4000000,2000, cur[0]+off,256,
                                   part, Rf+z*2048, 5, 400);
                    reduce_k<<<2000,256>>>(part, 2000*256, 5, 0,0, 0, Cf+z*2048, tc2+off, 0, 0);
                }
                run_gemm(0,0, 4000,256,256, cur[0],256, cg_w,256,        alt[0],256, cg_b,0,0,0,0,0,0,0,0,0);
                run_gemm(0,0, 4000,256,256, tc1,256,    cg_w+65536,256,  alt[0],256, 0,0,0,0,0,0,1,0,0,0);
                run_gemm(0,0, 4000,256,256, cur[1],256, cg_w,256,        alt[1],256, cg_b,0,0,0,0,0,0,0,0,0);
                run_gemm(0,0, 4000,256,256, tc2,256,    cg_w+65536,256,  alt[1],256, 0,0,0,0,0,0,1,0,0,0);
                float* t0 = cur[0]; cur[0] = alt[0]; alt[0] = t0;
                float* t1 = cur[1]; cur[1] = alt[1]; alt[1] = t1;
            }
            if (i == 2){
                write_s_k<<<dim3(16,4000),256>>>(out_s, s0, Rf, Cf);
            }
        }
    }
}

// round 6
// speedup vs baseline: 1.6357x; 1.6357x over previous
#include <cuda_runtime.h>
#include <cuda_bf16.h>
#include <cstdint>
#include <math.h>

// ---------------- static scratch (allocation-free rule) ----------------
__device__ float g_h   [2000*512];
__device__ float g_xA1 [4000*256];
__device__ float g_xB1 [4000*256];
__device__ float g_xA2 [4000*256];
__device__ float g_xB2 [4000*256];
__device__ float g_axu [4000*512];
__device__ float g_tc1 [4000*256];
__device__ float g_tc2 [4000*256];
__device__ float g_s0  [2u*2000*2000];
__device__ float g_T1  [2000*256];
__device__ float g_Ssym[256*256];
__device__ float g_wcat[256*512];
__device__ float g_bcat[512];
__device__ float g_cs  [2*4096];
__device__ float g_u   [2*2048];
__device__ float g_v   [2*2048];
__device__ float g_Rf  [2*2048];
__device__ float g_Cf  [2*2048];
__device__ float g_sq  [4*2048];
__device__ float g_gmax[2];
__device__ float g_part[5u*4000*256];                 // split-K partials
__device__ __nv_bfloat16 g_Abf[2ull*3*4096*4096];     // A 3-term bf16 (both graphs, padded)
__device__ __nv_bfloat16 g_Bbf[3ull*256*4096];        // ax^T 3-term bf16 (padded)

// ---------------- reductions ----------------
__device__ __forceinline__ float warpReduceSum(float v){
#pragma unroll
    for (int o=16;o;o>>=1) v += __shfl_xor_sync(0xffffffffu, v, o);
    return v;
}
__device__ __forceinline__ float warpReduceMax(float v){
#pragma unroll
    for (int o=16;o;o>>=1) v = fmaxf(v, __shfl_xor_sync(0xffffffffu, v, o));
    return v;
}
__device__ __forceinline__ float blockReduceSum256(float v){
    __shared__ float sm[8];
    float w = warpReduceSum(v);
    int wi = threadIdx.x>>5, ln = threadIdx.x&31;
    if (ln==0) sm[wi] = w;
    __syncthreads();
    if (wi==0){ float t = (ln<8)?sm[ln]:0.f; t = warpReduceSum(t); if (ln==0) sm[0]=t; }
    __syncthreads();
    float r = sm[0];
    __syncthreads();
    return r;
}
__device__ __forceinline__ float blockReduceMax256(float v){
    __shared__ float sm[8];
    float w = warpReduceMax(v);
    int wi = threadIdx.x>>5, ln = threadIdx.x&31;
    if (ln==0) sm[wi] = w;
    __syncthreads();
    if (wi==0){ float t = (ln<8)?sm[ln]:-1e30f; t = warpReduceMax(t); if (ln==0) sm[0]=t; }
    __syncthreads();
    float r = sm[0];
    __syncthreads();
    return r;
}

// ================= bf16 mma.sync big GEMM =================
// part[ks][m][n] = sum over 6 bf16 term-products of A[m,k]*B[n,k] for k in ks-chunk.
// Abf: [3][4096][4096] (row m, col k). Bbf: [3][256][4096] (row n, col k).
// grid (2 ntiles, 32 mtiles, 4 ksplits), 256 threads (8 warps, 4m x 2n of 32x64).
__device__ __forceinline__ void mma16816(float* d, const uint32_t* a, uint32_t b0, uint32_t b1){
    asm volatile(
        "mma.sync.aligned.m16n8k16.row.col.f32.bf16.bf16.f32 "
        "{%0,%1,%2,%3}, {%4,%5,%6,%7}, {%8,%9}, {%0,%1,%2,%3};"
        : "+f"(d[0]), "+f"(d[1]), "+f"(d[2]), "+f"(d[3])
        : "r"(a[0]), "r"(a[1]), "r"(a[2]), "r"(a[3]), "r"(b0), "r"(b1));
}

#define SM_ROW 40   // 32 k + 8 pad (bf16 elems); 80 B row stride, conflict-free
#define TERM_SZ (128*SM_ROW)
#define MMA_SMEM (2*3*TERM_SZ*2)   // 61440 bytes

__global__ void __launch_bounds__(256) mma_big_k(
    const __nv_bfloat16* __restrict__ Abf,
    const __nv_bfloat16* __restrict__ Bbf,
    float* __restrict__ part)
{
    extern __shared__ __nv_bfloat16 sm[];
    __nv_bfloat16* As = sm;                 // [3][128][SM_ROW]
    __nv_bfloat16* Bs = sm + 3*TERM_SZ;     // [3][128][SM_ROW]
    const int tid = threadIdx.x;
    const int lane = tid & 31, wid = tid >> 5;
    const int grp = lane >> 2, qid = lane & 3;
    const int warp_m = (wid & 3) * 32;
    const int warp_n = (wid >> 2) * 64;
    const int n0 = blockIdx.x * 128;
    const int m0 = blockIdx.y * 128;
    const int kbeg = blockIdx.z * 1024;

    float acc[2][8][4];
#pragma unroll
    for (int i=0;i<2;++i)
#pragma unroll
        for (int j=0;j<8;++j)
#pragma unroll
            for (int q=0;q<4;++q) acc[i][j][q] = 0.f;

    const int pA[6] = {0,0,1,1,0,2};
    const int pB[6] = {0,1,0,1,2,0};

    for (int k0 = kbeg; k0 < kbeg + 1024; k0 += 32){
        // ---- load 3 A terms (128x32) + 3 B terms (128x32) into padded smem ----
#pragma unroll
        for (int t=0; t<3; ++t){
#pragma unroll
            for (int it=0; it<2; ++it){
                int idx = it*256 + tid;          // 512 uint4 per term
                int r = idx >> 2, c8 = (idx & 3) << 3;
                uint4 va = *(const uint4*)(Abf + (size_t)t*16777216ull + (size_t)(m0+r)*4096 + k0 + c8);
                *(uint4*)(As + t*TERM_SZ + r*SM_ROW + c8) = va;
                uint4 vb = *(const uint4*)(Bbf + (size_t)t*1048576ull + (size_t)(n0+r)*4096 + k0 + c8);
                *(uint4*)(Bs + t*TERM_SZ + r*SM_ROW + c8) = vb;
            }
        }
        __syncthreads();
        // ---- compute: 2 k16 steps ----
#pragma unroll
        for (int kk=0; kk<32; kk+=16){
            uint32_t afr[3][2][4];
#pragma unroll
            for (int t=0; t<3; ++t)
#pragma unroll
                for (int mf=0; mf<2; ++mf){
                    const __nv_bfloat16* ap = As + t*TERM_SZ + (warp_m + mf*16 + grp)*SM_ROW + kk + qid*2;
                    afr[t][mf][0] = *(const uint32_t*)(ap);
                    afr[t][mf][1] = *(const uint32_t*)(ap + 8*SM_ROW);
                    afr[t][mf][2] = *(const uint32_t*)(ap + 8);
                    afr[t][mf][3] = *(const uint32_t*)(ap + 8*SM_ROW + 8);
                }
#pragma unroll
            for (int p=0; p<6; ++p){
                const __nv_bfloat16* bb = Bs + pB[p]*TERM_SZ + (warp_n + grp)*SM_ROW + kk + qid*2;
#pragma unroll
                for (int nf=0; nf<8; ++nf){
                    uint32_t b0 = *(const uint32_t*)(bb + nf*8*SM_ROW);
                    uint32_t b1 = *(const uint32_t*)(bb + nf*8*SM_ROW + 8);
                    mma16816(acc[0][nf], afr[pA[p]][0], b0, b1);
                    mma16816(acc[1][nf], afr[pA[p]][1], b0, b1);
                }
            }
        }
        __syncthreads();
    }

    // ---- epilogue: raw fp32 partials ----
    float* pb = part + (size_t)blockIdx.z * (4000*256);
#pragma unroll
    for (int mf=0; mf<2; ++mf){
        int gm0 = m0 + warp_m + mf*16 + grp;
        int gm1 = gm0 + 8;
#pragma unroll
        for (int nf=0; nf<8; ++nf){
            int gn = n0 + warp_n + nf*8 + qid*2;
            if (gm0 < 4000){
                float2 v0 = make_float2(acc[mf][nf][0], acc[mf][nf][1]);
                *(float2*)(pb + (size_t)gm0*256 + gn) = v0;
            }
            if (gm1 < 4000){
                float2 v1 = make_float2(acc[mf][nf][2], acc[mf][nf][3]);
                *(float2*)(pb + (size_t)gm1*256 + gn) = v1;
            }
        }
    }
}

// --------- conversion kernels ---------
__device__ __forceinline__ void bf3split(float a, __nv_bfloat16& b0, __nv_bfloat16& b1, __nv_bfloat16& b2){
    b0 = __float2bfloat16(a);
    float r1 = a - __bfloat162float(b0);
    b1 = __float2bfloat16(r1);
    float r2 = r1 - __bfloat162float(b1);
    b2 = __float2bfloat16(r2);
}
__device__ __forceinline__ uint32_t bfpack(__nv_bfloat16 lo, __nv_bfloat16 hi){
    return (uint32_t)__bfloat16_as_ushort(lo) | ((uint32_t)__bfloat16_as_ushort(hi) << 16);
}
// A[4000,4000] fp32 -> out[3][4096][4096] bf16 (zero padded). grid 8192, block 256.
__global__ void convA_k(const float* __restrict__ A, __nv_bfloat16* __restrict__ out){
    size_t t = (size_t)blockIdx.x*256 + threadIdx.x;    // < 4096*512
    int r  = (int)(t >> 9);
    int k8 = (int)(t & 511) << 3;
    bool rin = (r < 4000);
    float v[8];
#pragma unroll
    for (int i=0;i<8;++i){ int k = k8 + i; v[i] = (rin && k < 4000) ? A[(size_t)r*4000 + k] : 0.f; }
    uint32_t p0[4], p1[4], p2[4];
#pragma unroll
    for (int i=0;i<4;++i){
        __nv_bfloat16 a0,a1,a2,b0,b1,b2;
        bf3split(v[2*i],   a0,a1,a2);
        bf3split(v[2*i+1], b0,b1,b2);
        p0[i] = bfpack(a0,b0); p1[i] = bfpack(a1,b1); p2[i] = bfpack(a2,b2);
    }
    size_t o = (size_t)r*4096 + k8;
    *(uint4*)(out + o)               = make_uint4(p0[0],p0[1],p0[2],p0[3]);
    *(uint4*)(out + o + 16777216ull) = make_uint4(p1[0],p1[1],p1[2],p1[3]);
    *(uint4*)(out + o + 33554432ull) = make_uint4(p2[0],p2[1],p2[2],p2[3]);
}
// axu[4000,512] cols 0:256 (scaled by cs[k]) -> out[3][256][4096] bf16 transposed, padded.
// grid (128, 8), block (32, 8)
__global__ void convB_k(const float* __restrict__ axu, const float* __restrict__ cs,
                        __nv_bfloat16* __restrict__ out){
    __shared__ float tile[32][33];
    int kt = blockIdx.x*32, nt = blockIdx.y*32;
    int tx = threadIdx.x, ty = threadIdx.y;
    for (int i=ty; i<32; i+=8){
        int k = kt + i;
        tile[i][tx] = (k < 4000) ? axu[(size_t)k*512 + nt + tx] * cs[k] : 0.f;
    }
    __syncthreads();
    for (int i=ty; i<32; i+=8){
        int n = nt + i, k = kt + tx;
        float a = tile[tx][i];
        __nv_bfloat16 b0,b1,b2;
        bf3split(a, b0,b1,b2);
        size_t o = (size_t)n*4096 + k;
        out[o] = b0; out[o + 1048576ull] = b1; out[o + 2097152ull] = b2;
    }
}

// ---------------- generic fp32 GEMM (R2 version) ----------------
#define BM 128
#define BN 64
#define BK 16

template<bool TA, bool TB>
__global__ __launch_bounds__(256) void gemm_k(
    int M, int N, int K, int chunk, size_t pstride,
    const float* __restrict__ A, int lda,
    const float* __restrict__ B, int ldb,
    float* __restrict__ C, int ldc,
    const float* __restrict__ bias,
    const float* __restrict__ kscale,
    const float* __restrict__ mscale,
    const float* __restrict__ addend, int ldadd,
    int act, int accum,
    const float* __restrict__ xsq, const float* __restrict__ ysq,
    float* __restrict__ gmax)
{
    __shared__ float As[BK][BM+4];
    __shared__ float Bs[BK][BN+4];
    int tid = threadIdx.x;
    int m0 = blockIdx.y * BM;
    int n0 = blockIdx.x * BN;
    int tx = tid & 15, ty = tid >> 4;
    int ml = ty*8, nl = tx*4;

    int kbeg = blockIdx.z * chunk;
    int kend = kbeg + chunk; if (kend > K) kend = K;

    float acc[8][4];
#pragma unroll
    for (int i=0;i<8;++i)
#pragma unroll
        for (int j=0;j<4;++j) acc[i][j] = 0.f;

    for (int k0 = kbeg; k0 < kend; k0 += BK){
        if (!TA){
#pragma unroll
            for (int it=0; it<2; ++it){
                int idx = it*256 + tid;
                int row = idx >> 2;
                int kc  = (idx & 3) << 2;
                float4 vv = make_float4(0.f,0.f,0.f,0.f);
                int gm = m0 + row;
                if (gm < M) vv = *(const float4*)(A + (size_t)gm*lda + k0 + kc);
                As[kc+0][row]=vv.x; As[kc+1][row]=vv.y; As[kc+2][row]=vv.z; As[kc+3][row]=vv.w;
            }
        } else {
#pragma unroll
            for (int it=0; it<2; ++it){
                int idx = it*256 + tid;
                int kk = idx >> 5;
                int mc = (idx & 31) << 2;
                float4 vv = make_float4(0.f,0.f,0.f,0.f);
                int gm = m0 + mc;
                if (gm < M) vv = *(const float4*)(A + (size_t)(k0+kk)*lda + gm);
                *(float4*)(&As[kk][mc]) = vv;
            }
        }
        if (!TB){
            int kk = tid >> 4;
            int nc = (tid & 15) << 2;
            float4 vv = make_float4(0.f,0.f,0.f,0.f);
            int gn = n0 + nc;
            if (gn < N) vv = *(const float4*)(B + (size_t)(k0+kk)*ldb + gn);
            if (kscale){ float s = kscale[k0+kk]; vv.x*=s; vv.y*=s; vv.z*=s; vv.w*=s; }
            *(float4*)(&Bs[kk][nc]) = vv;
        } else {
            int nr = tid >> 2;
            int kc = (tid & 3) << 2;
            float4 vv = make_float4(0.f,0.f,0.f,0.f);
            int gn = n0 + nr;
            if (gn < N) vv = *(const float4*)(B + (size_t)gn*ldb + k0 + kc);
            if (kscale){
                vv.x *= kscale[k0+kc+0]; vv.y *= kscale[k0+kc+1];
                vv.z *= kscale[k0+kc+2]; vv.w *= kscale[k0+kc+3];
            }
            Bs[kc+0][nr]=vv.x; Bs[kc+1][nr]=vv.y; Bs[kc+2][nr]=vv.z; Bs[kc+3][nr]=vv.w;
        }
        __syncthreads();
#pragma unroll
        for (int kk=0; kk<BK; ++kk){
            float4 a0 = *(const float4*)(&As[kk][ml]);
            float4 a1 = *(const float4*)(&As[kk][ml+4]);
            float4 b0 = *(const float4*)(&Bs[kk][nl]);
            float av[8] = {a0.x,a0.y,a0.z,a0.w,a1.x,a1.y,a1.z,a1.w};
            float bv[4] = {b0.x,b0.y,b0.z,b0.w};
#pragma unroll
            for (int i=0;i<8;++i)
#pragma unroll
                for (int j=0;j<4;++j) acc[i][j] = fmaf(av[i], bv[j], acc[i][j]);
        }
        __syncthreads();
    }

    if (gridDim.z > 1){
        float* Cp = C + (size_t)blockIdx.z * pstride;
#pragma unroll
        for (int i=0;i<8;++i){
            int gm = m0 + ml + i;
            if (gm < M){
#pragma unroll
                for (int j=0;j<4;++j){
                    int gn = n0 + nl + j;
                    if (gn < N) Cp[(size_t)gm*ldc + gn] = acc[i][j];
                }
            }
        }
        return;
    }

    float dmax = 0.f;
#pragma unroll
    for (int i=0;i<8;++i){
        int gm = m0 + ml + i;
        if (gm < M){
#pragma unroll
            for (int j=0;j<4;++j){
                int gn = n0 + nl + j;
                if (gn < N){
                    float v = acc[i][j];
                    size_t cidx = (size_t)gm*ldc + gn;
                    if (accum)  v += C[cidx];
                    if (addend) v += addend[(size_t)gm*ldadd + gn];
                    if (bias)   v += bias[gn];
                    if (act==1)      v = fmaxf(v, 0.f);
                    else if (act==2) v = 1.f/(1.f+expf(-v));
                    else if (act==3){
                        v = sqrtf(fmaxf(xsq[gm]+ysq[gn]-2.f*v, 0.f));
                        dmax = fmaxf(dmax, v);
                    }
                    if (mscale) v *= mscale[gm];
                    C[cidx] = v;
                }
            }
        }
    }
    if (act==3){
        __shared__ float red[256];
        red[tid] = dmax; __syncthreads();
        for (int s=128;s;s>>=1){ if (tid<s) red[tid]=fmaxf(red[tid],red[tid+s]); __syncthreads(); }
        if (tid==0) atomicMax((int*)gmax, __float_as_int(red[0]));
    }
}

// ---------------- split-K reducer ----------------
__global__ void reduce_k(const float* __restrict__ part, size_t pstride, int SK,
                         const float* __restrict__ addend, int ldadd,
                         const float* __restrict__ bias,
                         const float* __restrict__ rowscale,
                         float* __restrict__ out,
                         float* __restrict__ sqout, int mode)
{
    int row = blockIdx.x, t = threadIdx.x;
    float v = 0.f;
    for (int z=0; z<SK; ++z) v += part[(size_t)z*pstride + (size_t)row*256 + t];
    if (addend) v += addend[(size_t)row*ldadd + t];
    if (bias)   v += bias[t];
    if (mode==1){
        float s = blockReduceSum256(v*v);
        v /= fmaxf(sqrtf(s), 1e-12f);
        if (sqout && t==0) sqout[row] = 1.f;
    } else if (mode==2){
        v = 1.f/(1.f+expf(-v));
        float s = blockReduceSum256(v*v);
        if (sqout && t==0) sqout[row] = s;
    }
    if (rowscale) v *= rowscale[row];
    out[(size_t)row*256 + t] = v;
}

// ---------------- elementwise / misc kernels ----------------
__global__ void zero_k(float* p, int n){
    int i = blockIdx.x*blockDim.x + threadIdx.x;
    if (i < n) p[i] = 0.f;
}
__global__ void recip_clamp_k(float* p, int n){
    int i = blockIdx.x*blockDim.x + threadIdx.x;
    if (i < n) p[i] = 1.f / fmaxf(p[i], 1e-12f);
}
__global__ void simfin_k(float* __restrict__ p, const float* __restrict__ gmax, int n){
    int i = blockIdx.x*blockDim.x + threadIdx.x;
    if (i < n){
        float inv = 1.f / gmax[0];
        p[i] = 1.f - p[i]*inv;
    }
}
__global__ void colabs_k(const float* __restrict__ A, float* __restrict__ acc){
    int j  = blockIdx.x*256 + threadIdx.x;
    int r0 = blockIdx.y*125;
    if (j >= 4000) return;
    float s = 0.f;
    for (int i=0;i<125;++i) s += fabsf(A[(size_t)(r0+i)*4000 + j]);
    atomicAdd(&acc[j], s);
}
__global__ void ssym_k(const float* __restrict__ A, float* __restrict__ S){
    int i = blockIdx.x, j = threadIdx.x;
    S[i*256+j] = 0.5f*(A[i*256+j] + A[j*256+i]);
}
__global__ void pack_k(const float* __restrict__ wa, const float* __restrict__ wu,
                       const float* __restrict__ ba, const float* __restrict__ bu,
                       float* __restrict__ wcat, float* __restrict__ bcat){
    int r = blockIdx.x, n = threadIdx.x;
    wcat[r*512 + n] = (n < 256) ? wa[r*256 + n] : wu[r*256 + (n-256)];
    if (r == 0) bcat[n] = (n < 256) ? ba[n] : bu[n-256];
}
__global__ void softmax_k(float* __restrict__ s0base){
    int z = blockIdx.y, row = blockIdx.x, tid = threadIdx.x;
    float* p = s0base + (size_t)z*4000000 + (size_t)row*2000;
    float a[8]; float mx = -1e30f;
#pragma unroll
    for (int i=0;i<8;++i){
        int c = tid + i*256;
        if (c < 2000){ a[i] = 200.f*p[c]; mx = fmaxf(mx, a[i]); }
        else a[i] = -1e30f;
    }
    float rowmax = blockReduceMax256(mx);
    float Mx = fmaxf(rowmax, 0.f);
    float lsum = 0.f;
#pragma unroll
    for (int i=0;i<8;++i){
        int c = tid + i*256;
        if (c < 2000){ a[i] = expf(a[i]-Mx); lsum += a[i]; }
    }
    float tot = blockReduceSum256(lsum) + 2000.f*expf(-Mx);
    float inv = 1.f/tot;
#pragma unroll
    for (int i=0;i<8;++i){
        int c = tid + i*256;
        if (c < 2000) p[c] = a[i]*inv + 1e-4f;
    }
}
__global__ void sink_col_k(const float* __restrict__ s0base, const float* __restrict__ vraw,
                           float* __restrict__ uraw, int first){
    int z = blockIdx.z;
    const float* s0 = s0base + (size_t)z*4000000;
    __shared__ float Rs[125];
    int r0 = blockIdx.y*125;
    if (threadIdx.x < 125)
        Rs[threadIdx.x] = first ? 1.f : 1.f/vraw[z*2048 + r0 + threadIdx.x];
    __syncthreads();
    int j = blockIdx.x*256 + threadIdx.x;
    if (j < 2000){
        float s = 0.f;
        for (int i=0;i<125;++i) s += s0[(size_t)(r0+i)*2000 + j]*Rs[i];
        atomicAdd(&uraw[z*2048 + j], s);
    }
}
__global__ void sink_row_k(const float* __restrict__ s0base, const float* __restrict__ uraw,
                           float* __restrict__ vraw){
    int z = blockIdx.y;
    const float* s0 = s0base + (size_t)z*4000000;
    __shared__ float Cs[2000];
    for (int i=threadIdx.x; i<2000; i+=256) Cs[i] = 1.f/uraw[z*2048 + i];
    __syncthreads();
    int w = threadIdx.x>>5, lane = threadIdx.x&31;
    int row = blockIdx.x*8 + w;
    const float* pr = s0 + (size_t)row*2000;
    float s = 0.f;
    for (int j=lane; j<2000; j+=32) s += pr[j]*Cs[j];
#pragma unroll
    for (int o=16;o;o>>=1) s += __shfl_down_sync(0xffffffffu, s, o);
    if (lane==0) vraw[z*2048 + row] = s;
}
__global__ void scales_k(const float* __restrict__ uraw, const float* __restrict__ vraw,
                         float* __restrict__ Cf, float* __restrict__ Rf){
    int z = blockIdx.y;
    int i = blockIdx.x*256 + threadIdx.x;
    if (i < 2000){
        Cf[z*2048+i] = 1.f/uraw[z*2048+i];
        Rf[z*2048+i] = 1.f/vraw[z*2048+i];
    }
}
__global__ void write_s_k(float* __restrict__ out, const float* __restrict__ s0base,
                          const float* __restrict__ Rf, const float* __restrict__ Cf){
    int row = blockIdx.y;
    int col = blockIdx.x*256 + threadIdx.x;
    if (col >= 4000) return;
    float v = 0.f;
    if (row < 2000 && col < 2000)
        v = s0base[(size_t)row*2000 + col] * Rf[row] * Cf[col];
    else if (row >= 2000 && col >= 2000)
        v = s0base[4000000 + (size_t)(row-2000)*2000 + (col-2000)]
            * Rf[2048 + row-2000] * Cf[2048 + col-2000];
    out[(size_t)row*4000 + col] = v;
}

// ---------------- host-side GEMM dispatch ----------------
static void run_gemm(int ta, int tb, int M, int N, int K,
                     const float* A, int lda, const float* B, int ldb,
                     float* C, int ldc,
                     const float* bias, const float* ks, const float* ms,
                     const float* add, int ldadd, int act, int accum,
                     const float* xsq, const float* ysq, float* gmax)
{
    dim3 grid((N+BN-1)/BN, (M+BM-1)/BM, 1);
    if (!ta && !tb)      gemm_k<false,false><<<grid,256>>>(M,N,K,K,0,A,lda,B,ldb,C,ldc,bias,ks,ms,add,ldadd,act,accum,xsq,ysq,gmax);
    else if (!ta && tb)  gemm_k<false,true ><<<grid,256>>>(M,N,K,K,0,A,lda,B,ldb,C,ldc,bias,ks,ms,add,ldadd,act,accum,xsq,ysq,gmax);
    else                 gemm_k<true ,false><<<grid,256>>>(M,N,K,K,0,A,lda,B,ldb,C,ldc,bias,ks,ms,add,ldadd,act,accum,xsq,ysq,gmax);
}
static void run_gemm_split(int ta, int M, int N, int K,
                           const float* A, int lda, const float* B, int ldb,
                           float* part, const float* ks, int SK, int chunk)
{
    dim3 grid((N+BN-1)/BN, (M+BM-1)/BM, SK);
    size_t ps = (size_t)M*N;
    if (!ta) gemm_k<false,false><<<grid,256>>>(M,N,K,chunk,ps,A,lda,B,ldb,part,N,0,ks,0,0,0,0,0,0,0,0);
    else     gemm_k<true ,false><<<grid,256>>>(M,N,K,chunk,ps,A,lda,B,ldb,part,N,0,ks,0,0,0,0,0,0,0,0);
}

extern "C" void kernel_launch(void* const* d_in, const int* in_sizes, int n_in,
                              void* d_out, int out_size)
{
    (void)in_sizes; (void)n_in; (void)out_size;
    const float* emb1      = (const float*)d_in[0];
    const float* emb2      = (const float*)d_in[1];
    const float* edge1     = (const float*)d_in[2];
    const float* edge2     = (const float*)d_in[3];
    const float* Asrc      = (const float*)d_in[4];
    const float* Atgt      = (const float*)d_in[5];
    const float* fc1n_w    = (const float*)d_in[6];
    const float* fc1n_b    = (const float*)d_in[7];
    const float* fc2n_w    = (const float*)d_in[8];
    const float* fc2n_b    = (const float*)d_in[9];
    const float* fc1e_w    = (const float*)d_in[10];
    const float* fc1e_b    = (const float*)d_in[11];
    const float* fc2e_w    = (const float*)d_in[12];
    const float* fc2e_b    = (const float*)d_in[13];
    const float* gnn_a_w   = (const float*)d_in[14];
    const float* gnn_a_b   = (const float*)d_in[15];
    const float* gnn_u_w   = (const float*)d_in[16];
    const float* gnn_u_b   = (const float*)d_in[17];
    const float* aff_A     = (const float*)d_in[18];
    const float* cg_w      = (const float*)d_in[19];
    const float* cg_b      = (const float*)d_in[20];

    float* out_s  = (float*)d_out;
    float* out_kp = out_s + 16000000;
    float* out_ke = out_s + 20000000;

    float *h,*xA1,*xB1,*xA2,*xB2,*axu,*tc1,*tc2,*s0,*T1,*Ssym,*wcat,*bcat;
    float *cs,*u,*v,*Rf,*Cf,*sq,*gmax,*part;
    __nv_bfloat16 *Abf, *Bbf;
    cudaGetSymbolAddress((void**)&h,    g_h);
    cudaGetSymbolAddress((void**)&xA1,  g_xA1);
    cudaGetSymbolAddress((void**)&xB1,  g_xB1);
    cudaGetSymbolAddress((void**)&xA2,  g_xA2);
    cudaGetSymbolAddress((void**)&xB2,  g_xB2);
    cudaGetSymbolAddress((void**)&axu,  g_axu);
    cudaGetSymbolAddress((void**)&tc1,  g_tc1);
    cudaGetSymbolAddress((void**)&tc2,  g_tc2);
    cudaGetSymbolAddress((void**)&s0,   g_s0);
    cudaGetSymbolAddress((void**)&T1,   g_T1);
    cudaGetSymbolAddress((void**)&Ssym, g_Ssym);
    cudaGetSymbolAddress((void**)&wcat, g_wcat);
    cudaGetSymbolAddress((void**)&bcat, g_bcat);
    cudaGetSymbolAddress((void**)&cs,   g_cs);
    cudaGetSymbolAddress((void**)&u,    g_u);
    cudaGetSymbolAddress((void**)&v,    g_v);
    cudaGetSymbolAddress((void**)&Rf,   g_Rf);
    cudaGetSymbolAddress((void**)&Cf,   g_Cf);
    cudaGetSymbolAddress((void**)&sq,   g_sq);
    cudaGetSymbolAddress((void**)&gmax, g_gmax);
    cudaGetSymbolAddress((void**)&part, g_part);
    cudaGetSymbolAddress((void**)&Abf,  g_Abf);
    cudaGetSymbolAddress((void**)&Bbf,  g_Bbf);

    cudaFuncSetAttribute(mma_big_k, cudaFuncAttributeMaxDynamicSharedMemorySize, MMA_SMEM);

    float* cur[2] = {xA1, xA2};
    float* alt[2] = {xB1, xB2};

    // ---------- A conversions (once; A is constant across layers) ----------
    convA_k<<<8192,256>>>(Asrc, Abf);
    convA_k<<<8192,256>>>(Atgt, Abf + 3ull*4096*4096);

    // ---------- Stage A: node/edge embedding MLPs ----------
    run_gemm(0,0, 2000,512,128, emb1,128, fc1n_w,512, h,512, fc1n_b,0,0,0,0,1,0,0,0,0);
    run_gemm_split(0, 2000,256,512, h,512, fc2n_w,256, part, 0, 4, 128);
    reduce_k<<<2000,256>>>(part, 2000*256, 4, 0,0, fc2n_b, 0, cur[0], sq+0, 1);
    run_gemm(0,0, 2000,512,128, emb2,128, fc1n_w,512, h,512, fc1n_b,0,0,0,0,1,0,0,0,0);
    run_gemm_split(0, 2000,256,512, h,512, fc2n_w,256, part, 0, 4, 128);
    reduce_k<<<2000,256>>>(part, 2000*256, 4, 0,0, fc2n_b, 0, cur[1], sq+2048, 1);
    run_gemm(0,0, 2000,512,128, edge1,128, fc1e_w,512, h,512, fc1e_b,0,0,0,0,1,0,0,0,0);
    run_gemm_split(0, 2000,256,512, h,512, fc2e_w,256, part, 0, 4, 128);
    reduce_k<<<2000,256>>>(part, 2000*256, 4, 0,0, fc2e_b, 0, cur[0]+2000*256, sq+4096, 2);
    run_gemm(0,0, 2000,512,128, edge2,128, fc1e_w,512, h,512, fc1e_b,0,0,0,0,1,0,0,0,0);
    run_gemm_split(0, 2000,256,512, h,512, fc2e_w,256, part, 0, 4, 128);
    reduce_k<<<2000,256>>>(part, 2000*256, 4, 0,0, fc2e_b, 0, cur[1]+2000*256, sq+6144, 2);

    // ---------- Kp / Ke pairwise similarity ----------
    zero_k<<<1,32>>>(gmax, 2);
    run_gemm(0,1, 2000,2000,256, cur[0],256, cur[1],256, out_kp,2000,
             0,0,0,0,0, 3,0, sq+0,   sq+2048, gmax+0);
    run_gemm(0,1, 2000,2000,256, cur[0]+2000*256,256, cur[1]+2000*256,256, out_ke,2000,
             0,0,0,0,0, 3,0, sq+4096, sq+6144, gmax+1);
    simfin_k<<<(4000000+255)/256,256>>>(out_kp, gmax+0, 4000000);
    simfin_k<<<(4000000+255)/256,256>>>(out_ke, gmax+1, 4000000);

    // ---------- A column L1 sums -> reciprocal scales ----------
    zero_k<<<(8192+255)/256,256>>>(cs, 8192);
    colabs_k<<<dim3(16,32),256>>>(Asrc, cs);
    colabs_k<<<dim3(16,32),256>>>(Atgt, cs+4096);
    recip_clamp_k<<<(8192+255)/256,256>>>(cs, 8192);

    // ---------- GNN layers ----------
    for (int i=0; i<3; ++i){
        pack_k<<<256,512>>>(gnn_a_w + (size_t)i*65536, gnn_u_w + (size_t)i*65536,
                            gnn_a_b + (size_t)i*256,   gnn_u_b + (size_t)i*256,
                            wcat, bcat);

        for (int g=0; g<2; ++g){
            // axu = relu(x @ [wa|wu] + [ba|bu])
            run_gemm(0,0, 4000,512,256, cur[g],256, wcat,512, axu,512, bcat,0,0,0,0,1,0,0,0,0);
            // convert ax (scaled by colsum recip) to 3-term bf16, transposed
            convB_k<<<dim3(128,8),dim3(32,8)>>>(axu, cs + g*4096, Bbf);
            // big GEMM on tensor pipe via mma.sync (split-K 4, raw fp32 partials)
            mma_big_k<<<dim3(2,32,4),256,MMA_SMEM>>>(Abf + (size_t)g*3*4096*4096, Bbf, part);
            // + ux, row L2 normalize
            reduce_k<<<4000,256>>>(part, 4000*256, 4, axu+256,512, 0, 0, alt[g], 0, 1);
            float* t_ = cur[g]; cur[g] = alt[g]; alt[g] = t_;
        }

        if (i >= 1){
            ssym_k<<<256,256>>>(aff_A + (size_t)i*65536, Ssym);
            for (int z=0; z<2; ++z){
                size_t off = (size_t)z*2000*256;
                run_gemm_split(0, 2000,256,256, cur[0]+off,256, Ssym,256, part, 0, 2, 128);
                reduce_k<<<2000,256>>>(part, 2000*256, 2, 0,0, 0, 0, T1, 0, 0);
                run_gemm(0,1, 2000,2000,256, T1,256, cur[1]+off,256, s0 + (size_t)z*4000000,2000,
                         0,0,0,0,0,0,0,0,0,0);
            }
            softmax_k<<<dim3(2000,2),256>>>(s0);
            for (int t=0; t<10; ++t){
                if ((t & 1) == 0){
                    zero_k<<<(4096+255)/256,256>>>(u, 4096);
                    sink_col_k<<<dim3(8,16,2),256>>>(s0, v, u, (t==0)?1:0);
                } else {
                    sink_row_k<<<dim3(250,2),256>>>(s0, u, v);
                }
            }
            scales_k<<<dim3(8,2),256>>>(u, v, Cf, Rf);

            if (i == 1){
                for (int z=0; z<2; ++z){
                    size_t off = (size_t)z*2000*256;
                    run_gemm_split(0, 2000,256,2000, s0+(size_t)z*4000000,2000, cur[1]+off,256,
                                   part, Cf+z*2048, 5, 400);
                    reduce_k<<<2000,256>>>(part, 2000*256, 5, 0,0, 0, Rf+z*2048, tc1+off, 0, 0);
                    run_gemm_split(1, 2000,256,2000, s0+(size_t)z*4000000,2000, cur[0]+off,256,
                                   part, Rf+z*2048, 5, 400);
                    reduce_k<<<2000,256>>>(part, 2000*256, 5, 0,0, 0, Cf+z*2048, tc2+off, 0, 0);
                }
                run_gemm(0,0, 4000,256,256, cur[0],256, cg_w,256,        alt[0],256, cg_b,0,0,0,0,0,0,0,0,0);
                run_gemm(0,0, 4000,256,256, tc1,256,    cg_w+65536,256,  alt[0],256, 0,0,0,0,0,0,1,0,0,0);
                run_gemm(0,0, 4000,256,256, cur[1],256, cg_w,256,        alt[1],256, cg_b,0,0,0,0,0,0,0,0,0);
                run_gemm(0,0, 4000,256,256, tc2,256,    cg_w+65536,256,  alt[1],256, 0,0,0,0,0,0,1,0,0,0);
                float* t0 = cur[0]; cur[0] = alt[0]; alt[0] = t0;
                float* t1 = cur[1]; cur[1] = alt[1]; alt[1] = t1;
            }
            if (i == 2){
                write_s_k<<<dim3(16,4000),256>>>(out_s, s0, Rf, Cf);
            }
        }
    }
}

// round 7
// speedup vs baseline: 1.7337x; 1.0599x over previous
#include <cuda_runtime.h>
#include <cuda_bf16.h>
#include <cstdint>
#include <math.h>

// ---------------- static scratch (allocation-free rule) ----------------
__device__ float g_h   [2000*512];
__device__ float g_xA1 [4000*256];
__device__ float g_xB1 [4000*256];
__device__ float g_xA2 [4000*256];
__device__ float g_xB2 [4000*256];
__device__ float g_axu [4000*512];
__device__ float g_tc1 [4000*256];
__device__ float g_tc2 [4000*256];
__device__ float g_s0  [2u*2000*2000];
__device__ float g_T1  [2000*256];
__device__ float g_Ssym[256*256];
__device__ float g_wcat[256*512];
__device__ float g_bcat[512];
__device__ float g_cs  [2*4096];
__device__ float g_u   [2*2048];
__device__ float g_v   [2*2048];
__device__ float g_Rf  [2*2048];
__device__ float g_Cf  [2*2048];
__device__ float g_sq  [4*2048];
__device__ float g_gmax[2];
__device__ float g_part[5u*4000*256];                 // split-K partials
__device__ __nv_bfloat16 g_Abf[2ull*3*4096*4096];     // A 3-term bf16 (both graphs, padded)
__device__ __nv_bfloat16 g_Bbf[3ull*256*4096];        // ax^T 3-term bf16 (padded)

// ---------------- reductions ----------------
__device__ __forceinline__ float warpReduceSum(float v){
#pragma unroll
    for (int o=16;o;o>>=1) v += __shfl_xor_sync(0xffffffffu, v, o);
    return v;
}
__device__ __forceinline__ float warpReduceMax(float v){
#pragma unroll
    for (int o=16;o;o>>=1) v = fmaxf(v, __shfl_xor_sync(0xffffffffu, v, o));
    return v;
}
__device__ __forceinline__ float blockReduceSum256(float v){
    __shared__ float sm[8];
    float w = warpReduceSum(v);
    int wi = threadIdx.x>>5, ln = threadIdx.x&31;
    if (ln==0) sm[wi] = w;
    __syncthreads();
    if (wi==0){ float t = (ln<8)?sm[ln]:0.f; t = warpReduceSum(t); if (ln==0) sm[0]=t; }
    __syncthreads();
    float r = sm[0];
    __syncthreads();
    return r;
}
__device__ __forceinline__ float blockReduceMax256(float v){
    __shared__ float sm[8];
    float w = warpReduceMax(v);
    int wi = threadIdx.x>>5, ln = threadIdx.x&31;
    if (ln==0) sm[wi] = w;
    __syncthreads();
    if (wi==0){ float t = (ln<8)?sm[ln]:-1e30f; t = warpReduceMax(t); if (ln==0) sm[0]=t; }
    __syncthreads();
    float r = sm[0];
    __syncthreads();
    return r;
}

// ================= bf16 mma.sync big GEMM (cp.async double-buffered) =======
__device__ __forceinline__ void mma16816(float* d, const uint32_t* a, uint32_t b0, uint32_t b1){
    asm volatile(
        "mma.sync.aligned.m16n8k16.row.col.f32.bf16.bf16.f32 "
        "{%0,%1,%2,%3}, {%4,%5,%6,%7}, {%8,%9}, {%0,%1,%2,%3};"
        : "+f"(d[0]), "+f"(d[1]), "+f"(d[2]), "+f"(d[3])
        : "r"(a[0]), "r"(a[1]), "r"(a[2]), "r"(a[3]), "r"(b0), "r"(b1));
}

#define SM_ROW 40                 // 32 k + 8 pad bf16 (80 B rows, 16B-aligned)
#define TERM_SZ (128*SM_ROW)
#define BUF_SZ  (6*TERM_SZ)       // elems per buffer: A 3 terms + B 3 terms
#define MMA_SMEM (2*BUF_SZ*2)     // 122880 bytes (double buffered)

__global__ void __launch_bounds__(256) mma_big_k(
    const __nv_bfloat16* __restrict__ Abf,
    const __nv_bfloat16* __restrict__ Bbf,
    float* __restrict__ part)
{
    extern __shared__ __nv_bfloat16 sm[];
    uint32_t smb;
    asm("{ .reg .u64 t; cvta.to.shared.u64 t, %1; cvt.u32.u64 %0, t; }" : "=r"(smb) : "l"(sm));
    const int tid = threadIdx.x;
    const int lane = tid & 31, wid = tid >> 5;
    const int grp = lane >> 2, qid = lane & 3;
    const int warp_m = (wid & 3) * 32;
    const int warp_n = (wid >> 2) * 64;
    const int n0 = blockIdx.x * 128;
    const int m0 = blockIdx.y * 128;
    const int kbeg = blockIdx.z * 1024;

    // per-thread staged-load coordinates (2 x uint4 per term per matrix)
    const int r0 = tid >> 2,         c8 = (tid & 3) << 3;
    const int r1 = (256 + tid) >> 2; // same c8

    float acc[2][8][4];
#pragma unroll
    for (int i=0;i<2;++i)
#pragma unroll
        for (int j=0;j<8;++j)
#pragma unroll
            for (int q=0;q<4;++q) acc[i][j][q] = 0.f;

    const int pA[6] = {0,0,1,1,0,2};
    const int pB[6] = {0,1,0,1,2,0};

    // ---- async prefetch of one 32-k tile into buffer `buf` ----
    auto prefetch = [&](int iter, int buf){
        int k0 = kbeg + iter*32;
        uint32_t base = smb + (uint32_t)(buf*BUF_SZ)*2;
#pragma unroll
        for (int t=0; t<3; ++t){
            const __nv_bfloat16* ga0 = Abf + (size_t)t*16777216ull + (size_t)(m0+r0)*4096 + k0 + c8;
            const __nv_bfloat16* ga1 = Abf + (size_t)t*16777216ull + (size_t)(m0+r1)*4096 + k0 + c8;
            uint32_t da0 = base + (uint32_t)(t*TERM_SZ + r0*SM_ROW + c8)*2;
            uint32_t da1 = base + (uint32_t)(t*TERM_SZ + r1*SM_ROW + c8)*2;
            asm volatile("cp.async.cg.shared.global [%0], [%1], 16;" :: "r"(da0), "l"(ga0));
            asm volatile("cp.async.cg.shared.global [%0], [%1], 16;" :: "r"(da1), "l"(ga1));
            const __nv_bfloat16* gb0 = Bbf + (size_t)t*1048576ull + (size_t)(n0+r0)*4096 + k0 + c8;
            const __nv_bfloat16* gb1 = Bbf + (size_t)t*1048576ull + (size_t)(n0+r1)*4096 + k0 + c8;
            uint32_t db0 = base + (uint32_t)((3+t)*TERM_SZ + r0*SM_ROW + c8)*2;
            uint32_t db1 = base + (uint32_t)((3+t)*TERM_SZ + r1*SM_ROW + c8)*2;
            asm volatile("cp.async.cg.shared.global [%0], [%1], 16;" :: "r"(db0), "l"(gb0));
            asm volatile("cp.async.cg.shared.global [%0], [%1], 16;" :: "r"(db1), "l"(gb1));
        }
        asm volatile("cp.async.commit_group;");
    };

    prefetch(0, 0);

    for (int it = 0; it < 32; ++it){
        if (it + 1 < 32){
            prefetch(it+1, (it+1)&1);
            asm volatile("cp.async.wait_group 1;");
        } else {
            asm volatile("cp.async.wait_group 0;");
        }
        __syncthreads();
        const __nv_bfloat16* As = sm + (it&1)*BUF_SZ;
        const __nv_bfloat16* Bs = As + 3*TERM_SZ;
#pragma unroll
        for (int kk=0; kk<32; kk+=16){
            uint32_t afr[3][2][4];
#pragma unroll
            for (int t=0; t<3; ++t)
#pragma unroll
                for (int mf=0; mf<2; ++mf){
                    const __nv_bfloat16* ap = As + t*TERM_SZ + (warp_m + mf*16 + grp)*SM_ROW + kk + qid*2;
                    afr[t][mf][0] = *(const uint32_t*)(ap);
                    afr[t][mf][1] = *(const uint32_t*)(ap + 8*SM_ROW);
                    afr[t][mf][2] = *(const uint32_t*)(ap + 8);
                    afr[t][mf][3] = *(const uint32_t*)(ap + 8*SM_ROW + 8);
                }
#pragma unroll
            for (int nf=0; nf<8; ++nf){
                const __nv_bfloat16* bb = Bs + (warp_n + nf*8 + grp)*SM_ROW + kk + qid*2;
                uint32_t b[3][2];
#pragma unroll
                for (int t=0; t<3; ++t){
                    b[t][0] = *(const uint32_t*)(bb + t*TERM_SZ);
                    b[t][1] = *(const uint32_t*)(bb + t*TERM_SZ + 8);
                }
#pragma unroll
                for (int p=0; p<6; ++p){
                    mma16816(acc[0][nf], afr[pA[p]][0], b[pB[p]][0], b[pB[p]][1]);
                    mma16816(acc[1][nf], afr[pA[p]][1], b[pB[p]][0], b[pB[p]][1]);
                }
            }
        }
        __syncthreads();
    }

    // ---- epilogue: raw fp32 partials ----
    float* pb = part + (size_t)blockIdx.z * (4000*256);
#pragma unroll
    for (int mf=0; mf<2; ++mf){
        int gm0 = m0 + warp_m + mf*16 + grp;
        int gm1 = gm0 + 8;
#pragma unroll
        for (int nf=0; nf<8; ++nf){
            int gn = n0 + warp_n + nf*8 + qid*2;
            if (gm0 < 4000){
                float2 v0 = make_float2(acc[mf][nf][0], acc[mf][nf][1]);
                *(float2*)(pb + (size_t)gm0*256 + gn) = v0;
            }
            if (gm1 < 4000){
                float2 v1 = make_float2(acc[mf][nf][2], acc[mf][nf][3]);
                *(float2*)(pb + (size_t)gm1*256 + gn) = v1;
            }
        }
    }
}

// --------- conversion kernels ---------
__device__ __forceinline__ void bf3split(float a, __nv_bfloat16& b0, __nv_bfloat16& b1, __nv_bfloat16& b2){
    b0 = __float2bfloat16(a);
    float r1 = a - __bfloat162float(b0);
    b1 = __float2bfloat16(r1);
    float r2 = r1 - __bfloat162float(b1);
    b2 = __float2bfloat16(r2);
}
__device__ __forceinline__ uint32_t bfpack(__nv_bfloat16 lo, __nv_bfloat16 hi){
    return (uint32_t)__bfloat16_as_ushort(lo) | ((uint32_t)__bfloat16_as_ushort(hi) << 16);
}
// A[4000,4000] fp32 -> out[3][4096][4096] bf16 (zero padded). grid 8192, block 256.
__global__ void convA_k(const float* __restrict__ A, __nv_bfloat16* __restrict__ out){
    size_t t = (size_t)blockIdx.x*256 + threadIdx.x;    // < 4096*512
    int r  = (int)(t >> 9);
    int k8 = (int)(t & 511) << 3;
    bool rin = (r < 4000);
    float v[8];
#pragma unroll
    for (int i=0;i<8;++i){ int k = k8 + i; v[i] = (rin && k < 4000) ? A[(size_t)r*4000 + k] : 0.f; }
    uint32_t p0[4], p1[4], p2[4];
#pragma unroll
    for (int i=0;i<4;++i){
        __nv_bfloat16 a0,a1,a2,b0,b1,b2;
        bf3split(v[2*i],   a0,a1,a2);
        bf3split(v[2*i+1], b0,b1,b2);
        p0[i] = bfpack(a0,b0); p1[i] = bfpack(a1,b1); p2[i] = bfpack(a2,b2);
    }
    size_t o = (size_t)r*4096 + k8;
    *(uint4*)(out + o)               = make_uint4(p0[0],p0[1],p0[2],p0[3]);
    *(uint4*)(out + o + 16777216ull) = make_uint4(p1[0],p1[1],p1[2],p1[3]);
    *(uint4*)(out + o + 33554432ull) = make_uint4(p2[0],p2[1],p2[2],p2[3]);
}
// axu[4000,512] cols 0:256 (scaled by cs[k]) -> out[3][256][4096] bf16 transposed, padded.
// grid (128, 8), block (32, 8)
__global__ void convB_k(const float* __restrict__ axu, const float* __restrict__ cs,
                        __nv_bfloat16* __restrict__ out){
    __shared__ float tile[32][33];
    int kt = blockIdx.x*32, nt = blockIdx.y*32;
    int tx = threadIdx.x, ty = threadIdx.y;
    for (int i=ty; i<32; i+=8){
        int k = kt + i;
        tile[i][tx] = (k < 4000) ? axu[(size_t)k*512 + nt + tx] * cs[k] : 0.f;
    }
    __syncthreads();
    for (int i=ty; i<32; i+=8){
        int n = nt + i, k = kt + tx;
        float a = tile[tx][i];
        __nv_bfloat16 b0,b1,b2;
        bf3split(a, b0,b1,b2);
        size_t o = (size_t)n*4096 + k;
        out[o] = b0; out[o + 1048576ull] = b1; out[o + 2097152ull] = b2;
    }
}

// ---------------- generic fp32 GEMM ----------------
#define BM 128
#define BN 64
#define BK 16

template<bool TA, bool TB>
__global__ __launch_bounds__(256) void gemm_k(
    int M, int N, int K, int chunk, size_t pstride,
    const float* __restrict__ A, int lda,
    const float* __restrict__ B, int ldb,
    float* __restrict__ C, int ldc,
    const float* __restrict__ bias,
    const float* __restrict__ kscale,
    const float* __restrict__ mscale,
    const float* __restrict__ addend, int ldadd,
    int act, int accum,
    const float* __restrict__ xsq, const float* __restrict__ ysq,
    float* __restrict__ gmax)
{
    __shared__ float As[BK][BM+4];
    __shared__ float Bs[BK][BN+4];
    int tid = threadIdx.x;
    int m0 = blockIdx.y * BM;
    int n0 = blockIdx.x * BN;
    int tx = tid & 15, ty = tid >> 4;
    int ml = ty*8, nl = tx*4;

    int kbeg = blockIdx.z * chunk;
    int kend = kbeg + chunk; if (kend > K) kend = K;

    float acc[8][4];
#pragma unroll
    for (int i=0;i<8;++i)
#pragma unroll
        for (int j=0;j<4;++j) acc[i][j] = 0.f;

    for (int k0 = kbeg; k0 < kend; k0 += BK){
        if (!TA){
#pragma unroll
            for (int it=0; it<2; ++it){
                int idx = it*256 + tid;
                int row = idx >> 2;
                int kc  = (idx & 3) << 2;
                float4 vv = make_float4(0.f,0.f,0.f,0.f);
                int gm = m0 + row;
                if (gm < M) vv = *(const float4*)(A + (size_t)gm*lda + k0 + kc);
                As[kc+0][row]=vv.x; As[kc+1][row]=vv.y; As[kc+2][row]=vv.z; As[kc+3][row]=vv.w;
            }
        } else {
#pragma unroll
            for (int it=0; it<2; ++it){
                int idx = it*256 + tid;
                int kk = idx >> 5;
                int mc = (idx & 31) << 2;
                float4 vv = make_float4(0.f,0.f,0.f,0.f);
                int gm = m0 + mc;
                if (gm < M) vv = *(const float4*)(A + (size_t)(k0+kk)*lda + gm);
                *(float4*)(&As[kk][mc]) = vv;
            }
        }
        if (!TB){
            int kk = tid >> 4;
            int nc = (tid & 15) << 2;
            float4 vv = make_float4(0.f,0.f,0.f,0.f);
            int gn = n0 + nc;
            if (gn < N) vv = *(const float4*)(B + (size_t)(k0+kk)*ldb + gn);
            if (kscale){ float s = kscale[k0+kk]; vv.x*=s; vv.y*=s; vv.z*=s; vv.w*=s; }
            *(float4*)(&Bs[kk][nc]) = vv;
        } else {
            int nr = tid >> 2;
            int kc = (tid & 3) << 2;
            float4 vv = make_float4(0.f,0.f,0.f,0.f);
            int gn = n0 + nr;
            if (gn < N) vv = *(const float4*)(B + (size_t)gn*ldb + k0 + kc);
            if (kscale){
                vv.x *= kscale[k0+kc+0]; vv.y *= kscale[k0+kc+1];
                vv.z *= kscale[k0+kc+2]; vv.w *= kscale[k0+kc+3];
            }
            Bs[kc+0][nr]=vv.x; Bs[kc+1][nr]=vv.y; Bs[kc+2][nr]=vv.z; Bs[kc+3][nr]=vv.w;
        }
        __syncthreads();
#pragma unroll
        for (int kk=0; kk<BK; ++kk){
            float4 a0 = *(const float4*)(&As[kk][ml]);
            float4 a1 = *(const float4*)(&As[kk][ml+4]);
            float4 b0 = *(const float4*)(&Bs[kk][nl]);
            float av[8] = {a0.x,a0.y,a0.z,a0.w,a1.x,a1.y,a1.z,a1.w};
            float bv[4] = {b0.x,b0.y,b0.z,b0.w};
#pragma unroll
            for (int i=0;i<8;++i)
#pragma unroll
                for (int j=0;j<4;++j) acc[i][j] = fmaf(av[i], bv[j], acc[i][j]);
        }
        __syncthreads();
    }

    if (gridDim.z > 1){
        float* Cp = C + (size_t)blockIdx.z * pstride;
#pragma unroll
        for (int i=0;i<8;++i){
            int gm = m0 + ml + i;
            if (gm < M){
#pragma unroll
                for (int j=0;j<4;++j){
                    int gn = n0 + nl + j;
                    if (gn < N) Cp[(size_t)gm*ldc + gn] = acc[i][j];
                }
            }
        }
        return;
    }

    float dmax = 0.f;
#pragma unroll
    for (int i=0;i<8;++i){
        int gm = m0 + ml + i;
        if (gm < M){
#pragma unroll
            for (int j=0;j<4;++j){
                int gn = n0 + nl + j;
                if (gn < N){
                    float v = acc[i][j];
                    size_t cidx = (size_t)gm*ldc + gn;
                    if (accum)  v += C[cidx];
                    if (addend) v += addend[(size_t)gm*ldadd + gn];
                    if (bias)   v += bias[gn];
                    if (act==1)      v = fmaxf(v, 0.f);
                    else if (act==2) v = 1.f/(1.f+expf(-v));
                    else if (act==3){
                        v = sqrtf(fmaxf(xsq[gm]+ysq[gn]-2.f*v, 0.f));
                        dmax = fmaxf(dmax, v);
                    }
                    if (mscale) v *= mscale[gm];
                    C[cidx] = v;
                }
            }
        }
    }
    if (act==3){
        __shared__ float red[256];
        red[tid] = dmax; __syncthreads();
        for (int s=128;s;s>>=1){ if (tid<s) red[tid]=fmaxf(red[tid],red[tid+s]); __syncthreads(); }
        if (tid==0) atomicMax((int*)gmax, __float_as_int(red[0]));
    }
}

// ---------------- split-K reducer ----------------
__global__ void reduce_k(const float* __restrict__ part, size_t pstride, int SK,
                         const float* __restrict__ addend, int ldadd,
                         const float* __restrict__ bias,
                         const float* __restrict__ rowscale,
                         float* __restrict__ out,
                         float* __restrict__ sqout, int mode)
{
    int row = blockIdx.x, t = threadIdx.x;
    float v = 0.f;
    for (int z=0; z<SK; ++z) v += part[(size_t)z*pstride + (size_t)row*256 + t];
    if (addend) v += addend[(size_t)row*ldadd + t];
    if (bias)   v += bias[t];
    if (mode==1){
        float s = blockReduceSum256(v*v);
        v /= fmaxf(sqrtf(s), 1e-12f);
        if (sqout && t==0) sqout[row] = 1.f;
    } else if (mode==2){
        v = 1.f/(1.f+expf(-v));
        float s = blockReduceSum256(v*v);
        if (sqout && t==0) sqout[row] = s;
    }
    if (rowscale) v *= rowscale[row];
    out[(size_t)row*256 + t] = v;
}

// ---------------- elementwise / misc kernels ----------------
__global__ void zero_k(float* p, int n){
    int i = blockIdx.x*blockDim.x + threadIdx.x;
    if (i < n) p[i] = 0.f;
}
__global__ void recip_clamp_k(float* p, int n){
    int i = blockIdx.x*blockDim.x + threadIdx.x;
    if (i < n) p[i] = 1.f / fmaxf(p[i], 1e-12f);
}
__global__ void simfin_k(float* __restrict__ p, const float* __restrict__ gmax, int n){
    int i = blockIdx.x*blockDim.x + threadIdx.x;
    if (i < n){
        float inv = 1.f / gmax[0];
        p[i] = 1.f - p[i]*inv;
    }
}
__global__ void colabs_k(const float* __restrict__ A, float* __restrict__ acc){
    int j  = blockIdx.x*256 + threadIdx.x;
    int r0 = blockIdx.y*125;
    if (j >= 4000) return;
    float s = 0.f;
    for (int i=0;i<125;++i) s += fabsf(A[(size_t)(r0+i)*4000 + j]);
    atomicAdd(&acc[j], s);
}
__global__ void ssym_k(const float* __restrict__ A, float* __restrict__ S){
    int i = blockIdx.x, j = threadIdx.x;
    S[i*256+j] = 0.5f*(A[i*256+j] + A[j*256+i]);
}
__global__ void pack_k(const float* __restrict__ wa, const float* __restrict__ wu,
                       const float* __restrict__ ba, const float* __restrict__ bu,
                       float* __restrict__ wcat, float* __restrict__ bcat){
    int r = blockIdx.x, n = threadIdx.x;
    wcat[r*512 + n] = (n < 256) ? wa[r*256 + n] : wu[r*256 + (n-256)];
    if (r == 0) bcat[n] = (n < 256) ? ba[n] : bu[n-256];
}
__global__ void softmax_k(float* __restrict__ s0base){
    int z = blockIdx.y, row = blockIdx.x, tid = threadIdx.x;
    float* p = s0base + (size_t)z*4000000 + (size_t)row*2000;
    float a[8]; float mx = -1e30f;
#pragma unroll
    for (int i=0;i<8;++i){
        int c = tid + i*256;
        if (c < 2000){ a[i] = 200.f*p[c]; mx = fmaxf(mx, a[i]); }
        else a[i] = -1e30f;
    }
    float rowmax = blockReduceMax256(mx);
    float Mx = fmaxf(rowmax, 0.f);
    float lsum = 0.f;
#pragma unroll
    for (int i=0;i<8;++i){
        int c = tid + i*256;
        if (c < 2000){ a[i] = expf(a[i]-Mx); lsum += a[i]; }
    }
    float tot = blockReduceSum256(lsum) + 2000.f*expf(-Mx);
    float inv = 1.f/tot;
#pragma unroll
    for (int i=0;i<8;++i){
        int c = tid + i*256;
        if (c < 2000) p[c] = a[i]*inv + 1e-4f;
    }
}
__global__ void sink_col_k(const float* __restrict__ s0base, const float* __restrict__ vraw,
                           float* __restrict__ uraw, int first){
    int z = blockIdx.z;
    const float* s0 = s0base + (size_t)z*4000000;
    __shared__ float Rs[125];
    int r0 = blockIdx.y*125;
    if (threadIdx.x < 125)
        Rs[threadIdx.x] = first ? 1.f : 1.f/vraw[z*2048 + r0 + threadIdx.x];
    __syncthreads();
    int j = blockIdx.x*256 + threadIdx.x;
    if (j < 2000){
        float s = 0.f;
        for (int i=0;i<125;++i) s += s0[(size_t)(r0+i)*2000 + j]*Rs[i];
        atomicAdd(&uraw[z*2048 + j], s);
    }
}
__global__ void sink_row_k(const float* __restrict__ s0base, const float* __restrict__ uraw,
                           float* __restrict__ vraw){
    int z = blockIdx.y;
    const float* s0 = s0base + (size_t)z*4000000;
    __shared__ float Cs[2000];
    for (int i=threadIdx.x; i<2000; i+=256) Cs[i] = 1.f/uraw[z*2048 + i];
    __syncthreads();
    int w = threadIdx.x>>5, lane = threadIdx.x&31;
    int row = blockIdx.x*8 + w;
    const float* pr = s0 + (size_t)row*2000;
    float s = 0.f;
    for (int j=lane; j<2000; j+=32) s += pr[j]*Cs[j];
#pragma unroll
    for (int o=16;o;o>>=1) s += __shfl_down_sync(0xffffffffu, s, o);
    if (lane==0) vraw[z*2048 + row] = s;
}
__global__ void scales_k(const float* __restrict__ uraw, const float* __restrict__ vraw,
                         float* __restrict__ Cf, float* __restrict__ Rf){
    int z = blockIdx.y;
    int i = blockIdx.x*256 + threadIdx.x;
    if (i < 2000){
        Cf[z*2048+i] = 1.f/uraw[z*2048+i];
        Rf[z*2048+i] = 1.f/vraw[z*2048+i];
    }
}
__global__ void write_s_k(float* __restrict__ out, const float* __restrict__ s0base,
                          const float* __restrict__ Rf, const float* __restrict__ Cf){
    int row = blockIdx.y;
    int col = blockIdx.x*256 + threadIdx.x;
    if (col >= 4000) return;
    float v = 0.f;
    if (row < 2000 && col < 2000)
        v = s0base[(size_t)row*2000 + col] * Rf[row] * Cf[col];
    else if (row >= 2000 && col >= 2000)
        v = s0base[4000000 + (size_t)(row-2000)*2000 + (col-2000)]
            * Rf[2048 + row-2000] * Cf[2048 + col-2000];
    out[(size_t)row*4000 + col] = v;
}

// ---------------- host-side GEMM dispatch ----------------
static void run_gemm(int ta, int tb, int M, int N, int K,
                     const float* A, int lda, const float* B, int ldb,
                     float* C, int ldc,
                     const float* bias, const float* ks, const float* ms,
                     const float* add, int ldadd, int act, int accum,
                     const float* xsq, const float* ysq, float* gmax)
{
    dim3 grid((N+BN-1)/BN, (M+BM-1)/BM, 1);
    if (!ta && !tb)      gemm_k<false,false><<<grid,256>>>(M,N,K,K,0,A,lda,B,ldb,C,ldc,bias,ks,ms,add,ldadd,act,accum,xsq,ysq,gmax);
    else if (!ta && tb)  gemm_k<false,true ><<<grid,256>>>(M,N,K,K,0,A,lda,B,ldb,C,ldc,bias,ks,ms,add,ldadd,act,accum,xsq,ysq,gmax);
    else                 gemm_k<true ,false><<<grid,256>>>(M,N,K,K,0,A,lda,B,ldb,C,ldc,bias,ks,ms,add,ldadd,act,accum,xsq,ysq,gmax);
}
static void run_gemm_split(int ta, int M, int N, int K,
                           const float* A, int lda, const float* B, int ldb,
                           float* part, const float* ks, int SK, int chunk)
{
    dim3 grid((N+BN-1)/BN, (M+BM-1)/BM, SK);
    size_t ps = (size_t)M*N;
    if (!ta) gemm_k<false,false><<<grid,256>>>(M,N,K,chunk,ps,A,lda,B,ldb,part,N,0,ks,0,0,0,0,0,0,0,0);
    else     gemm_k<true ,false><<<grid,256>>>(M,N,K,chunk,ps,A,lda,B,ldb,part,N,0,ks,0,0,0,0,0,0,0,0);
}

extern "C" void kernel_launch(void* const* d_in, const int* in_sizes, int n_in,
                              void* d_out, int out_size)
{
    (void)in_sizes; (void)n_in; (void)out_size;
    const float* emb1      = (const float*)d_in[0];
    const float* emb2      = (const float*)d_in[1];
    const float* edge1     = (const float*)d_in[2];
    const float* edge2     = (const float*)d_in[3];
    const float* Asrc      = (const float*)d_in[4];
    const float* Atgt      = (const float*)d_in[5];
    const float* fc1n_w    = (const float*)d_in[6];
    const float* fc1n_b    = (const float*)d_in[7];
    const float* fc2n_w    = (const float*)d_in[8];
    const float* fc2n_b    = (const float*)d_in[9];
    const float* fc1e_w    = (const float*)d_in[10];
    const float* fc1e_b    = (const float*)d_in[11];
    const float* fc2e_w    = (const float*)d_in[12];
    const float* fc2e_b    = (const float*)d_in[13];
    const float* gnn_a_w   = (const float*)d_in[14];
    const float* gnn_a_b   = (const float*)d_in[15];
    const float* gnn_u_w   = (const float*)d_in[16];
    const float* gnn_u_b   = (const float*)d_in[17];
    const float* aff_A     = (const float*)d_in[18];
    const float* cg_w      = (const float*)d_in[19];
    const float* cg_b      = (const float*)d_in[20];

    float* out_s  = (float*)d_out;
    float* out_kp = out_s + 16000000;
    float* out_ke = out_s + 20000000;

    float *h,*xA1,*xB1,*xA2,*xB2,*axu,*tc1,*tc2,*s0,*T1,*Ssym,*wcat,*bcat;
    float *cs,*u,*v,*Rf,*Cf,*sq,*gmax,*part;
    __nv_bfloat16 *Abf, *Bbf;
    cudaGetSymbolAddress((void**)&h,    g_h);
    cudaGetSymbolAddress((void**)&xA1,  g_xA1);
    cudaGetSymbolAddress((void**)&xB1,  g_xB1);
    cudaGetSymbolAddress((void**)&xA2,  g_xA2);
    cudaGetSymbolAddress((void**)&xB2,  g_xB2);
    cudaGetSymbolAddress((void**)&axu,  g_axu);
    cudaGetSymbolAddress((void**)&tc1,  g_tc1);
    cudaGetSymbolAddress((void**)&tc2,  g_tc2);
    cudaGetSymbolAddress((void**)&s0,   g_s0);
    cudaGetSymbolAddress((void**)&T1,   g_T1);
    cudaGetSymbolAddress((void**)&Ssym, g_Ssym);
    cudaGetSymbolAddress((void**)&wcat, g_wcat);
    cudaGetSymbolAddress((void**)&bcat, g_bcat);
    cudaGetSymbolAddress((void**)&cs,   g_cs);
    cudaGetSymbolAddress((void**)&u,    g_u);
    cudaGetSymbolAddress((void**)&v,    g_v);
    cudaGetSymbolAddress((void**)&Rf,   g_Rf);
    cudaGetSymbolAddress((void**)&Cf,   g_Cf);
    cudaGetSymbolAddress((void**)&sq,   g_sq);
    cudaGetSymbolAddress((void**)&gmax, g_gmax);
    cudaGetSymbolAddress((void**)&part, g_part);
    cudaGetSymbolAddress((void**)&Abf,  g_Abf);
    cudaGetSymbolAddress((void**)&Bbf,  g_Bbf);

    cudaFuncSetAttribute(mma_big_k, cudaFuncAttributeMaxDynamicSharedMemorySize, MMA_SMEM);

    float* cur[2] = {xA1, xA2};
    float* alt[2] = {xB1, xB2};

    // ---------- A conversions (once; A is constant across layers) ----------
    convA_k<<<8192,256>>>(Asrc, Abf);
    convA_k<<<8192,256>>>(Atgt, Abf + 3ull*4096*4096);

    // ---------- Stage A: node/edge embedding MLPs ----------
    run_gemm(0,0, 2000,512,128, emb1,128, fc1n_w,512, h,512, fc1n_b,0,0,0,0,1,0,0,0,0);
    run_gemm_split(0, 2000,256,512, h,512, fc2n_w,256, part, 0, 4, 128);
    reduce_k<<<2000,256>>>(part, 2000*256, 4, 0,0, fc2n_b, 0, cur[0], sq+0, 1);
    run_gemm(0,0, 2000,512,128, emb2,128, fc1n_w,512, h,512, fc1n_b,0,0,0,0,1,0,0,0,0);
    run_gemm_split(0, 2000,256,512, h,512, fc2n_w,256, part, 0, 4, 128);
    reduce_k<<<2000,256>>>(part, 2000*256, 4, 0,0, fc2n_b, 0, cur[1], sq+2048, 1);
    run_gemm(0,0, 2000,512,128, edge1,128, fc1e_w,512, h,512, fc1e_b,0,0,0,0,1,0,0,0,0);
    run_gemm_split(0, 2000,256,512, h,512, fc2e_w,256, part, 0, 4, 128);
    reduce_k<<<2000,256>>>(part, 2000*256, 4, 0,0, fc2e_b, 0, cur[0]+2000*256, sq+4096, 2);
    run_gemm(0,0, 2000,512,128, edge2,128, fc1e_w,512, h,512, fc1e_b,0,0,0,0,1,0,0,0,0);
    run_gemm_split(0, 2000,256,512, h,512, fc2e_w,256, part, 0, 4, 128);
    reduce_k<<<2000,256>>>(part, 2000*256, 4, 0,0, fc2e_b, 0, cur[1]+2000*256, sq+6144, 2);

    // ---------- Kp / Ke pairwise similarity ----------
    zero_k<<<1,32>>>(gmax, 2);
    run_gemm(0,1, 2000,2000,256, cur[0],256, cur[1],256, out_kp,2000,
             0,0,0,0,0, 3,0, sq+0,   sq+2048, gmax+0);
    run_gemm(0,1, 2000,2000,256, cur[0]+2000*256,256, cur[1]+2000*256,256, out_ke,2000,
             0,0,0,0,0, 3,0, sq+4096, sq+6144, gmax+1);
    simfin_k<<<(4000000+255)/256,256>>>(out_kp, gmax+0, 4000000);
    simfin_k<<<(4000000+255)/256,256>>>(out_ke, gmax+1, 4000000);

    // ---------- A column L1 sums -> reciprocal scales ----------
    zero_k<<<(8192+255)/256,256>>>(cs, 8192);
    colabs_k<<<dim3(16,32),256>>>(Asrc, cs);
    colabs_k<<<dim3(16,32),256>>>(Atgt, cs+4096);
    recip_clamp_k<<<(8192+255)/256,256>>>(cs, 8192);

    // ---------- GNN layers ----------
    for (int i=0; i<3; ++i){
        pack_k<<<256,512>>>(gnn_a_w + (size_t)i*65536, gnn_u_w + (size_t)i*65536,
                            gnn_a_b + (size_t)i*256,   gnn_u_b + (size_t)i*256,
                            wcat, bcat);

        for (int g=0; g<2; ++g){
            // axu = relu(x @ [wa|wu] + [ba|bu])
            run_gemm(0,0, 4000,512,256, cur[g],256, wcat,512, axu,512, bcat,0,0,0,0,1,0,0,0,0);
            // convert ax (scaled by colsum recip) to 3-term bf16, transposed
            convB_k<<<dim3(128,8),dim3(32,8)>>>(axu, cs + g*4096, Bbf);
            // big GEMM on tensor pipe via mma.sync (split-K 4, raw fp32 partials)
            mma_big_k<<<dim3(2,32,4),256,MMA_SMEM>>>(Abf + (size_t)g*3*4096*4096, Bbf, part);
            // + ux, row L2 normalize
            reduce_k<<<4000,256>>>(part, 4000*256, 4, axu+256,512, 0, 0, alt[g], 0, 1);
            float* t_ = cur[g]; cur[g] = alt[g]; alt[g] = t_;
        }

        if (i >= 1){
            ssym_k<<<256,256>>>(aff_A + (size_t)i*65536, Ssym);
            for (int z=0; z<2; ++z){
                size_t off = (size_t)z*2000*256;
                run_gemm_split(0, 2000,256,256, cur[0]+off,256, Ssym,256, part, 0, 2, 128);
                reduce_k<<<2000,256>>>(part, 2000*256, 2, 0,0, 0, 0, T1, 0, 0);
                run_gemm(0,1, 2000,2000,256, T1,256, cur[1]+off,256, s0 + (size_t)z*4000000,2000,
                         0,0,0,0,0,0,0,0,0,0);
            }
            softmax_k<<<dim3(2000,2),256>>>(s0);
            for (int t=0; t<10; ++t){
                if ((t & 1) == 0){
                    zero_k<<<(4096+255)/256,256>>>(u, 4096);
                    sink_col_k<<<dim3(8,16,2),256>>>(s0, v, u, (t==0)?1:0);
                } else {
                    sink_row_k<<<dim3(250,2),256>>>(s0, u, v);
                }
            }
            scales_k<<<dim3(8,2),256>>>(u, v, Cf, Rf);

            if (i == 1){
                for (int z=0; z<2; ++z){
                    size_t off = (size_t)z*2000*256;
                    run_gemm_split(0, 2000,256,2000, s0+(size_t)z*4000000,2000, cur[1]+off,256,
                                   part, Cf+z*2048, 5, 400);
                    reduce_k<<<2000,256>>>(part, 2000*256, 5, 0,0, 0, Rf+z*2048, tc1+off, 0, 0);
                    run_gemm_split(1, 2000,256,2000, s0+(size_t)z*4000000,2000, cur[0]+off,256,
                                   part, Rf+z*2048, 5, 400);
                    reduce_k<<<2000,256>>>(part, 2000*256, 5, 0,0, 0, Cf+z*2048, tc2+off, 0, 0);
                }
                run_gemm(0,0, 4000,256,256, cur[0],256, cg_w,256,        alt[0],256, cg_b,0,0,0,0,0,0,0,0,0);
                run_gemm(0,0, 4000,256,256, tc1,256,    cg_w+65536,256,  alt[0],256, 0,0,0,0,0,0,1,0,0,0);
                run_gemm(0,0, 4000,256,256, cur[1],256, cg_w,256,        alt[1],256, cg_b,0,0,0,0,0,0,0,0,0);
                run_gemm(0,0, 4000,256,256, tc2,256,    cg_w+65536,256,  alt[1],256, 0,0,0,0,0,0,1,0,0,0);
                float* t0 = cur[0]; cur[0] = alt[0]; alt[0] = t0;
                float* t1 = cur[1]; cur[1] = alt[1]; alt[1] = t1;
            }
            if (i == 2){
                write_s_k<<<dim3(16,4000),256>>>(out_s, s0, Rf, Cf);
            }
        }
    }
}